// round 14
// baseline (speedup 1.0000x reference)
#include <cuda_runtime.h>
#include <cuda_fp16.h>
#include <math.h>
#include <stdint.h>

#define BATCH 2
#define SEQ   2048
#define DM    1024
#define NH    16
#define NKV   4
#define DK    64
#define QKVN  1536
#define ROWS  (BATCH*SEQ)
#define GROUPS (NH/NKV)
#define GK    1024

// ---------------- scratch: pre-swizzled 16KB panels (128 rows x 64 fp16 cols) ----------------
__device__ __align__(128) uint32_t g_xhi[ROWS * GK / 2],  g_xlo[ROWS * GK / 2];
__device__ __align__(128) uint32_t g_wh [2560 * GK / 2];
__device__ __align__(128) uint32_t g_ahi[ROWS * DM / 2],  g_alo[ROWS * DM / 2];
__device__ __align__(128) uint32_t g_qh [BATCH * NH  * SEQ * DK / 2];
__device__ __align__(128) uint32_t g_kh [BATCH * NKV * SEQ * DK / 2];
__device__ __align__(128) uint32_t g_vh [BATCH * NKV * SEQ * DK / 2];

// ================= helpers =================
__device__ __forceinline__ uint32_t smem_to_u32(const void* p) {
    uint32_t a;
    asm("{ .reg .u64 t; cvta.to.shared.u64 t, %1; cvt.u32.u64 %0, t; }" : "=r"(a) : "l"(p));
    return a;
}
__device__ __forceinline__ float ex2(float x) {
    float r; asm("ex2.approx.f32 %0, %1;" : "=f"(r) : "f"(x)); return r;
}
__device__ __forceinline__ uint32_t pack_h2(float lo, float hi) {
    uint32_t r;
    asm("cvt.rn.f16x2.f32 %0, %1, %2;" : "=r"(r) : "f"(hi), "f"(lo));
    return r;
}
__device__ __forceinline__ void splitH2(float2 v, uint32_t& hi, uint32_t& lo) {
    __half h0 = __float2half_rn(v.x);
    __half h1 = __float2half_rn(v.y);
    float r0 = v.x - __half2float(h0);
    float r1 = v.y - __half2float(h1);
    hi = (uint32_t)__half_as_ushort(h0) | ((uint32_t)__half_as_ushort(h1) << 16);
    lo = pack_h2(r0, r1);
}
__device__ __forceinline__ uint32_t panel_u32(uint32_t panel, int r, int cp) {
    int cl = cp >> 2;
    return panel * 4096u + (uint32_t)(r * 32 + ((cl ^ (r & 7)) << 2) + (cp & 3));
}

__device__ __forceinline__ void bulk_cp(uint32_t dst, const void* src, uint32_t bytes, uint32_t mbar) {
    asm volatile("cp.async.bulk.shared::cta.global.mbarrier::complete_tx::bytes [%0], [%1], %2, [%3];"
        :: "r"(dst), "l"(src), "r"(bytes), "r"(mbar) : "memory");
}
#define MBARRIER_INIT(mbar, count) \
    asm volatile("mbarrier.init.shared.b64 [%0], %1;" \
        :: "r"((uint32_t)(mbar)), "r"((uint32_t)(count)) : "memory")
#define MBARRIER_EXPECT_TX(mbar, bytes) \
    asm volatile("mbarrier.arrive.expect_tx.shared.b64 _, [%0], %1;" \
        :: "r"((uint32_t)(mbar)), "r"((uint32_t)(bytes)) : "memory")
#define MBARRIER_WAIT(mbar_addr, parity) do { \
    uint32_t _mbar = (uint32_t)(mbar_addr); \
    uint32_t _par = (uint32_t)(parity); \
    uint32_t _done; \
    asm volatile("{\n\t.reg .pred p;\n\t" \
        "mbarrier.try_wait.parity.acquire.cta.shared::cta.b64 p, [%1], %2;\n\t" \
        "selp.b32 %0, 1, 0, p;\n\t}" : "=r"(_done) : "r"(_mbar), "r"(_par) : "memory"); \
    if (!_done) { \
        asm volatile("{\n\t.reg .pred P1;\n\t" \
            "WAIT_LOOP_%=:\n\t" \
            "mbarrier.try_wait.parity.acquire.cta.shared::cta.b64 P1, [%0], %1, 0x989680;\n\t" \
            "@P1 bra.uni WAIT_DONE_%=;\n\t" \
            "bra.uni WAIT_LOOP_%=;\n\t" \
            "WAIT_DONE_%=:\n\t}" :: "r"(_mbar), "r"(_par) : "memory"); \
    } \
} while(0)

__device__ __forceinline__ void ldsm4(uint32_t* r, uint32_t addr) {
    asm volatile("ldmatrix.sync.aligned.m8n8.x4.shared.b16 {%0,%1,%2,%3}, [%4];"
        : "=r"(r[0]), "=r"(r[1]), "=r"(r[2]), "=r"(r[3]) : "r"(addr));
}
__device__ __forceinline__ void ldsm4t(uint32_t* r, uint32_t addr) {
    asm volatile("ldmatrix.sync.aligned.m8n8.x4.trans.shared.b16 {%0,%1,%2,%3}, [%4];"
        : "=r"(r[0]), "=r"(r[1]), "=r"(r[2]), "=r"(r[3]) : "r"(addr));
}
__device__ __forceinline__ void mma16816h(float* c, const uint32_t* a, uint32_t b0, uint32_t b1) {
    asm volatile("mma.sync.aligned.m16n8k16.row.col.f32.f16.f16.f32 "
        "{%0,%1,%2,%3}, {%4,%5,%6,%7}, {%8,%9}, {%0,%1,%2,%3};"
        : "+f"(c[0]), "+f"(c[1]), "+f"(c[2]), "+f"(c[3])
        : "r"(a[0]), "r"(a[1]), "r"(a[2]), "r"(a[3]), "r"(b0), "r"(b1));
}

// ================= split / pack into panel layout =================
__global__ void split_f16_panel(const float* __restrict__ src, uint32_t* __restrict__ hi,
                                uint32_t* __restrict__ lo, int npairs) {
    int i = blockIdx.x * blockDim.x + threadIdx.x;
    if (i < npairs) {
        float2 v = ((const float2*)src)[i];
        uint32_t h, l;
        splitH2(v, h, l);
        int row = i >> 9, cp = i & 511;
        uint32_t idx = panel_u32((uint32_t)((row >> 7) * 16 + (cp >> 5)), row & 127, cp & 31);
        hi[idx] = h;
        lo[idx] = l;
    }
}
__global__ void pack_f16_panel(const float* __restrict__ src, uint32_t* __restrict__ dst, int npairs) {
    int i = blockIdx.x * blockDim.x + threadIdx.x;
    if (i < npairs) {
        float2 v = ((const float2*)src)[i];
        int row = i >> 9, cp = i & 511;
        uint32_t idx = panel_u32((uint32_t)((row >> 7) * 16 + (cp >> 5)), row & 127, cp & 31);
        dst[idx] = pack_h2(v.x, v.y);
    }
}

// ================= fp16x2 GEMM, 128x128 tile, 256 threads, 4-stage bulk pipeline =================
// warp grid 4m x 2n; warp tile 32m x 64n. B ldsm shared across 2 m-blocks.
// smem reads per k-step: A 64KB + B 64KB = 128KB (vs 192KB in 16-warp version).
template<bool FUSE_QKV>
__global__ __launch_bounds__(256, 1) void gemm_f16x2(
        const uint32_t* __restrict__ Ahi, const uint32_t* __restrict__ Alo,
        const uint32_t* __restrict__ Bh, float* __restrict__ C, int N,
        const float* __restrict__ qw, const float* __restrict__ kw) {
    extern __shared__ char smc[];
    const uint32_t sb = smem_to_u32(smc);
    const uint32_t MB = sb + 196608u;
    const int tid = threadIdx.x;
    const int wid = tid >> 5, lane = tid & 31;
    const int wm = wid & 3, wn = wid >> 2;
    const int mt = blockIdx.y, nt = blockIdx.x;

    if (tid == 0) {
        #pragma unroll
        for (int s = 0; s < 4; s++) MBARRIER_INIT(MB + s * 8, 1);
    }
    __syncthreads();

    auto issue = [&](int s, int kt) {
        MBARRIER_EXPECT_TX(MB + s * 8, 49152);
        bulk_cp(sb + s * 49152u,          Ahi + (size_t)(mt * 16 + kt) * 4096, 16384, MB + s * 8);
        bulk_cp(sb + s * 49152u + 16384u, Alo + (size_t)(mt * 16 + kt) * 4096, 16384, MB + s * 8);
        bulk_cp(sb + s * 49152u + 32768u, Bh  + (size_t)(nt * 16 + kt) * 4096, 16384, MB + s * 8);
    };
    if (tid == 0) { issue(0, 0); issue(1, 1); issue(2, 2); issue(3, 3); }

    float acc[2][8][4];
    #pragma unroll
    for (int i = 0; i < 2; i++)
        #pragma unroll
        for (int j = 0; j < 8; j++)
            #pragma unroll
            for (int e = 0; e < 4; e++) acc[i][j][e] = 0.0f;

    const int lrow = lane & 15, khalf = lane >> 4;

    for (int kt = 0; kt < 16; kt++) {
        MBARRIER_WAIT(MB + (kt & 3) * 8, (kt >> 2) & 1);
        const uint32_t base = sb + (uint32_t)(kt & 3) * 49152u;
        const uint32_t aHi = base, aLo = base + 16384u, bH = base + 32768u;

        #pragma unroll
        for (int ks = 0; ks < 4; ks++) {
            const int c = ks * 2 + khalf;
            uint32_t ah[2][4], al[2][4];
            #pragma unroll
            for (int ma = 0; ma < 2; ma++) {
                int r = wm * 32 + ma * 16 + lrow;
                uint32_t off = (uint32_t)(r * 128 + ((c ^ (r & 7)) << 4));
                ldsm4(ah[ma], aHi + off);
                ldsm4(al[ma], aLo + off);
            }
            #pragma unroll
            for (int nb = 0; nb < 4; nb++) {
                int r = wn * 64 + nb * 16 + lrow;
                uint32_t off = (uint32_t)(r * 128 + ((c ^ (r & 7)) << 4));
                uint32_t bh[4];
                ldsm4(bh, bH + off);
                #pragma unroll
                for (int ma = 0; ma < 2; ma++) {
                    mma16816h(acc[ma][nb * 2],     ah[ma], bh[0], bh[2]);
                    mma16816h(acc[ma][nb * 2],     al[ma], bh[0], bh[2]);
                    mma16816h(acc[ma][nb * 2 + 1], ah[ma], bh[1], bh[3]);
                    mma16816h(acc[ma][nb * 2 + 1], al[ma], bh[1], bh[3]);
                }
            }
        }
        __syncthreads();
        if (tid == 0 && kt + 4 < 16) issue(kt & 3, kt + 4);
    }

    const int crow = lane >> 2, ccl = lane & 3;

    if (!FUSE_QKV) {
        const int ccol = ccl * 2;
        #pragma unroll
        for (int ma = 0; ma < 2; ma++) {
            #pragma unroll
            for (int na = 0; na < 8; na++) {
                int r = mt * 128 + wm * 32 + ma * 16 + crow;
                int cc = nt * 128 + wn * 64 + na * 8 + ccol;
                *(float2*)&C[(size_t)r * N + cc]       = make_float2(acc[ma][na][0], acc[ma][na][1]);
                *(float2*)&C[(size_t)(r + 8) * N + cc] = make_float2(acc[ma][na][2], acc[ma][na][3]);
            }
        }
        return;
    }

    // ---------- fused RMSNorm + RoPE + fp16 panel epilogue ----------
    const int slot = nt * 2 + wn;      // one full head per warp

    if (slot >= NH + NKV) {            // V panels
        const int hv = slot - NH - NKV;
        #pragma unroll
        for (int ma = 0; ma < 2; ma++)
            #pragma unroll
            for (int rr = 0; rr < 2; rr++) {
                const int row = mt * 128 + wm * 32 + ma * 16 + rr * 8 + crow;
                const int b = row >> 11, t = row & (SEQ - 1);
                const uint32_t pan = (uint32_t)((b * NKV + hv) * 16 + (t >> 7));
                const int r = t & 127;
                #pragma unroll
                for (int na = 0; na < 8; na++)
                    g_vh[panel_u32(pan, r, na * 4 + ccl)] =
                        pack_h2(acc[ma][na][rr * 2], acc[ma][na][rr * 2 + 1]);
            }
        return;
    }

    const bool isQ = (slot < NH);
    const float* w = isQ ? qw : kw;
    float w0[8], w1[8], invf[8];
    #pragma unroll
    for (int na = 0; na < 8; na++) {
        const int i = na * 4 + ccl;
        w0[na] = w[2 * i];
        w1[na] = w[2 * i + 1];
        invf[na] = __powf(10000.0f, -(float)(2 * i) / (float)DK);
    }
    const float qs = 0.125f * 1.4426950408889634f;

    #pragma unroll
    for (int ma = 0; ma < 2; ma++)
        #pragma unroll
        for (int rr = 0; rr < 2; rr++) {
            const int row = mt * 128 + wm * 32 + ma * 16 + rr * 8 + crow;
            const int b = row >> 11, t = row & (SEQ - 1);

            float ss = 0.0f;
            #pragma unroll
            for (int na = 0; na < 8; na++) {
                float v0 = acc[ma][na][rr * 2], v1 = acc[ma][na][rr * 2 + 1];
                ss += v0 * v0 + v1 * v1;
            }
            ss += __shfl_xor_sync(0xffffffffu, ss, 1);
            ss += __shfl_xor_sync(0xffffffffu, ss, 2);
            const float rnorm = rsqrtf(ss * (1.0f / DK) + 1.1920929e-07f);

            const uint32_t pan = isQ
                ? (uint32_t)((b * NH + slot) * 16 + (t >> 7))
                : (uint32_t)((b * NKV + (slot - NH)) * 16 + (t >> 7));
            const int r = t & 127;

            #pragma unroll
            for (int na = 0; na < 8; na++) {
                float y0 = acc[ma][na][rr * 2]     * rnorm * w0[na];
                float y1 = acc[ma][na][rr * 2 + 1] * rnorm * w1[na];
                float sv, cv;
                sincosf((float)t * invf[na], &sv, &cv);
                float o0 = y0 * cv - y1 * sv;
                float o1 = y0 * sv + y1 * cv;
                if (isQ) g_qh[panel_u32(pan, r, na * 4 + ccl)] = pack_h2(o0 * qs, o1 * qs);
                else     g_kh[panel_u32(pan, r, na * 4 + ccl)] = pack_h2(o0, o1);
            }
        }
}

// ================= tensor-core causal flash attention (unchanged from R13) =================
__global__ __launch_bounds__(256, 1) void attn_mma() {
    extern __shared__ char sma[];
    const uint32_t sb = smem_to_u32(sma);
    const uint32_t MB = sb + 81920u;
    const int tid = threadIdx.x;
    const int wid = tid >> 5, lane = tid & 31;
    const int wq = wid >> 1, wk = wid & 1;
    const int qb = (int)gridDim.x - 1 - (int)blockIdx.x;
    const int h  = blockIdx.y, b = blockIdx.z;
    const int kvh = h / GROUPS;
    const int nkb = qb + 1;

    if (tid == 0) {
        MBARRIER_INIT(MB + 0, 1);
        MBARRIER_INIT(MB + 8, 1);
        MBARRIER_INIT(MB + 16, 1);
    }
    __syncthreads();

    const uint32_t qpan  = (uint32_t)((b * NH + h) * 16 + qb);
    const uint32_t kvpan = (uint32_t)((b * NKV + kvh) * 16);

    auto issue = [&](int s, int kb) {
        MBARRIER_EXPECT_TX(MB + s * 8, 32768);
        bulk_cp(sb + s * 32768u,          g_kh + (size_t)(kvpan + kb) * 4096, 16384, MB + s * 8);
        bulk_cp(sb + s * 32768u + 16384u, g_vh + (size_t)(kvpan + kb) * 4096, 16384, MB + s * 8);
    };
    if (tid == 0) {
        MBARRIER_EXPECT_TX(MB + 16, 16384);
        bulk_cp(sb + 65536u, g_qh + (size_t)qpan * 4096, 16384, MB + 16);
        issue(0, 0);
        if (nkb > 1) issue(1, 1);
    }

    MBARRIER_WAIT(MB + 16, 0);
    const int lrow = lane & 15, khalf = lane >> 4;
    uint32_t qh[2][4][4];
    #pragma unroll
    for (int rb = 0; rb < 2; rb++) {
        const int r = wq * 32 + rb * 16 + lrow;
        #pragma unroll
        for (int ks = 0; ks < 4; ks++) {
            const int c = ks * 2 + khalf;
            uint32_t off = (uint32_t)(r * 128 + ((c ^ (r & 7)) << 4));
            ldsm4(qh[rb][ks], sb + 65536u + off);
        }
    }

    float oa[2][8][4];
    #pragma unroll
    for (int rb = 0; rb < 2; rb++)
        #pragma unroll
        for (int j = 0; j < 8; j++)
            #pragma unroll
            for (int e = 0; e < 4; e++) oa[rb][j][e] = 0.0f;
    float lsum[2][2] = {{0.0f, 0.0f}, {0.0f, 0.0f}};

    const int vrow_base = ((lane >> 3) & 1) * 8 + (lane & 7);
    const int vkh = lane >> 4;

    for (int kb = 0; kb < nkb; kb++) {
        MBARRIER_WAIT(MB + (kb & 1) * 8, (kb >> 1) & 1);
        const uint32_t kH = sb + (uint32_t)(kb & 1) * 32768u;
        const uint32_t vH = kH + 16384u;

        float sc[2][8][4];
        #pragma unroll
        for (int rb = 0; rb < 2; rb++)
            #pragma unroll
            for (int j = 0; j < 8; j++)
                #pragma unroll
                for (int e = 0; e < 4; e++) sc[rb][j][e] = 0.0f;

        #pragma unroll
        for (int ks = 0; ks < 4; ks++) {
            const int c = ks * 2 + khalf;
            #pragma unroll
            for (int nb = 0; nb < 4; nb++) {
                int r = wk * 64 + nb * 16 + lrow;
                uint32_t off = (uint32_t)(r * 128 + ((c ^ (r & 7)) << 4));
                uint32_t kh[4];
                ldsm4(kh, kH + off);
                #pragma unroll
                for (int rb = 0; rb < 2; rb++) {
                    mma16816h(sc[rb][2 * nb],     qh[rb][ks], kh[0], kh[2]);
                    mma16816h(sc[rb][2 * nb + 1], qh[rb][ks], kh[1], kh[3]);
                }
            }
        }

        if (kb == qb) {
            #pragma unroll
            for (int rb = 0; rb < 2; rb++) {
                const int g0 = qb * 128 + wq * 32 + rb * 16 + (lane >> 2);
                const int g1 = g0 + 8;
                #pragma unroll
                for (int j = 0; j < 8; j++) {
                    const int c0 = kb * 128 + wk * 64 + 8 * j + (lane & 3) * 2;
                    const int c1 = c0 + 1;
                    if (c0 > g0) sc[rb][j][0] = -INFINITY;
                    if (c1 > g0) sc[rb][j][1] = -INFINITY;
                    if (c0 > g1) sc[rb][j][2] = -INFINITY;
                    if (c1 > g1) sc[rb][j][3] = -INFINITY;
                }
            }
        }

        #pragma unroll
        for (int rb = 0; rb < 2; rb++) {
            #pragma unroll
            for (int j = 0; j < 8; j++) {
                sc[rb][j][0] = ex2(sc[rb][j][0]);
                sc[rb][j][1] = ex2(sc[rb][j][1]);
                sc[rb][j][2] = ex2(sc[rb][j][2]);
                sc[rb][j][3] = ex2(sc[rb][j][3]);
                lsum[rb][0] += sc[rb][j][0] + sc[rb][j][1];
                lsum[rb][1] += sc[rb][j][2] + sc[rb][j][3];
            }
        }

        uint32_t pa[2][4][4];
        #pragma unroll
        for (int rb = 0; rb < 2; rb++)
            #pragma unroll
            for (int kk = 0; kk < 4; kk++) {
                pa[rb][kk][0] = pack_h2(sc[rb][2 * kk][0],     sc[rb][2 * kk][1]);
                pa[rb][kk][1] = pack_h2(sc[rb][2 * kk][2],     sc[rb][2 * kk][3]);
                pa[rb][kk][2] = pack_h2(sc[rb][2 * kk + 1][0], sc[rb][2 * kk + 1][1]);
                pa[rb][kk][3] = pack_h2(sc[rb][2 * kk + 1][2], sc[rb][2 * kk + 1][3]);
            }

        #pragma unroll
        for (int kk = 0; kk < 4; kk++) {
            const int vr = wk * 64 + kk * 16 + vrow_base;
            #pragma unroll
            for (int ng = 0; ng < 4; ng++) {
                const int vc = ng * 2 + vkh;
                uint32_t off = (uint32_t)(vr * 128 + ((vc ^ (vr & 7)) << 4));
                uint32_t vh[4];
                ldsm4t(vh, vH + off);
                #pragma unroll
                for (int rb = 0; rb < 2; rb++) {
                    mma16816h(oa[rb][2 * ng],     pa[rb][kk], vh[0], vh[1]);
                    mma16816h(oa[rb][2 * ng + 1], pa[rb][kk], vh[2], vh[3]);
                }
            }
        }
        __syncthreads();
        if (tid == 0 && kb + 2 < nkb) issue(kb & 1, kb + 2);
    }

    #pragma unroll
    for (int rb = 0; rb < 2; rb++) {
        lsum[rb][0] += __shfl_xor_sync(0xffffffffu, lsum[rb][0], 1);
        lsum[rb][0] += __shfl_xor_sync(0xffffffffu, lsum[rb][0], 2);
        lsum[rb][1] += __shfl_xor_sync(0xffffffffu, lsum[rb][1], 1);
        lsum[rb][1] += __shfl_xor_sync(0xffffffffu, lsum[rb][1], 2);
    }

    float* xch = (float*)sma;
    __syncthreads();
    if (wk == 1) {
        float* dst = xch + (wq * 32 + lane) * 68;
        #pragma unroll
        for (int rb = 0; rb < 2; rb++)
            #pragma unroll
            for (int j = 0; j < 8; j++) {
                dst[rb * 32 + j * 4 + 0] = oa[rb][j][0];
                dst[rb * 32 + j * 4 + 1] = oa[rb][j][1];
                dst[rb * 32 + j * 4 + 2] = oa[rb][j][2];
                dst[rb * 32 + j * 4 + 3] = oa[rb][j][3];
            }
        dst[64] = lsum[0][0]; dst[65] = lsum[0][1];
        dst[66] = lsum[1][0]; dst[67] = lsum[1][1];
    }
    __syncthreads();
    if (wk == 1) return;

    {
        const float* src = xch + (wq * 32 + lane) * 68;
        #pragma unroll
        for (int rb = 0; rb < 2; rb++)
            #pragma unroll
            for (int j = 0; j < 8; j++) {
                oa[rb][j][0] += src[rb * 32 + j * 4 + 0];
                oa[rb][j][1] += src[rb * 32 + j * 4 + 1];
                oa[rb][j][2] += src[rb * 32 + j * 4 + 2];
                oa[rb][j][3] += src[rb * 32 + j * 4 + 3];
            }
        lsum[0][0] += src[64]; lsum[0][1] += src[65];
        lsum[1][0] += src[66]; lsum[1][1] += src[67];
    }

    #pragma unroll
    for (int rb = 0; rb < 2; rb++) {
        const float inv0 = 1.0f / lsum[rb][0], inv1 = 1.0f / lsum[rb][1];
        const int t0 = qb * 128 + wq * 32 + rb * 16 + (lane >> 2);
        const int t1 = t0 + 8;
        const uint32_t pan = (uint32_t)((b * 16 + qb) * 16 + h);
        const int r0 = t0 & 127, r1 = t1 & 127;
        #pragma unroll
        for (int j = 0; j < 8; j++) {
            const int cp = j * 4 + (lane & 3);
            uint32_t hi, lo;
            splitH2(make_float2(oa[rb][j][0] * inv0, oa[rb][j][1] * inv0), hi, lo);
            uint32_t i0 = panel_u32(pan, r0, cp);
            g_ahi[i0] = hi; g_alo[i0] = lo;
            splitH2(make_float2(oa[rb][j][2] * inv1, oa[rb][j][3] * inv1), hi, lo);
            uint32_t i1 = panel_u32(pan, r1, cp);
            g_ahi[i1] = hi; g_alo[i1] = lo;
        }
    }
}

// ================= launch =================
extern "C" void kernel_launch(void* const* d_in, const int* in_sizes, int n_in,
                              void* d_out, int out_size) {
    const float* x    = (const float*)d_in[0];
    const float* qkvo = (const float*)d_in[1];
    const float* qw   = (const float*)d_in[2];
    const float* kw   = (const float*)d_in[3];
    float* out = (float*)d_out;

    void *p_xhi, *p_xlo, *p_wh, *p_ahi, *p_alo;
    cudaGetSymbolAddress(&p_xhi, g_xhi); cudaGetSymbolAddress(&p_xlo, g_xlo);
    cudaGetSymbolAddress(&p_wh, g_wh);
    cudaGetSymbolAddress(&p_ahi, g_ahi); cudaGetSymbolAddress(&p_alo, g_alo);

    const int GEMM_SMEM = 4 * 49152 + 64;
    const int ATTN_SMEM = 81920 + 64;
    cudaFuncSetAttribute(gemm_f16x2<true>,  cudaFuncAttributeMaxDynamicSharedMemorySize, GEMM_SMEM);
    cudaFuncSetAttribute(gemm_f16x2<false>, cudaFuncAttributeMaxDynamicSharedMemorySize, GEMM_SMEM);
    cudaFuncSetAttribute(attn_mma, cudaFuncAttributeMaxDynamicSharedMemorySize, ATTN_SMEM);

    // 0) split x (hi/lo) and pack weights into panel layout
    {
        int np = ROWS * GK / 2;
        split_f16_panel<<<np / 256, 256>>>(x, (uint32_t*)p_xhi, (uint32_t*)p_xlo, np);
        int nw = 2560 * GK / 2;
        pack_f16_panel<<<nw / 256, 256>>>(qkvo, (uint32_t*)p_wh, nw);
    }

    // 1) QKV projection + fused RMSNorm/RoPE -> Q/K/V fp16 panels
    gemm_f16x2<true><<<dim3(QKVN / 128, ROWS / 128), 256, GEMM_SMEM>>>(
        (const uint32_t*)p_xhi, (const uint32_t*)p_xlo,
        (const uint32_t*)p_wh, nullptr, QKVN, qw, kw);

    // 2) tensor-core causal flash attention -> g_ahi/g_alo panels
    attn_mma<<<dim3(SEQ / 128, NH, BATCH), 256, ATTN_SMEM>>>();

    // 3) O projection (weights panels start at nt=12)
    gemm_f16x2<false><<<dim3(DM / 128, ROWS / 128), 256, GEMM_SMEM>>>(
        (const uint32_t*)p_ahi, (const uint32_t*)p_alo,
        (const uint32_t*)p_wh + (size_t)12 * 16 * 4096, out, DM, nullptr, nullptr);
}

// round 15
// speedup vs baseline: 1.2279x; 1.2279x over previous
#include <cuda_runtime.h>
#include <cuda_fp16.h>
#include <math.h>
#include <stdint.h>

#define BATCH 2
#define SEQ   2048
#define DM    1024
#define NH    16
#define NKV   4
#define DK    64
#define QKVN  1536
#define ROWS  (BATCH*SEQ)
#define GROUPS (NH/NKV)
#define GK    1024

// ---------------- scratch: pre-swizzled 16KB panels (128 rows x 64 fp16 cols) ----------------
__device__ __align__(128) uint32_t g_xhi[ROWS * GK / 2],  g_xlo[ROWS * GK / 2];
__device__ __align__(128) uint32_t g_wh [2560 * GK / 2];
__device__ __align__(128) uint32_t g_ah [ROWS * DM / 2];            // attn out single fp16
__device__ __align__(128) uint32_t g_qh [BATCH * NH  * SEQ * DK / 2];
__device__ __align__(128) uint32_t g_kh [BATCH * NKV * SEQ * DK / 2];
__device__ __align__(128) uint32_t g_vh [BATCH * NKV * SEQ * DK / 2];

// ================= helpers =================
__device__ __forceinline__ uint32_t smem_to_u32(const void* p) {
    uint32_t a;
    asm("{ .reg .u64 t; cvta.to.shared.u64 t, %1; cvt.u32.u64 %0, t; }" : "=r"(a) : "l"(p));
    return a;
}
__device__ __forceinline__ float ex2(float x) {
    float r; asm("ex2.approx.f32 %0, %1;" : "=f"(r) : "f"(x)); return r;
}
__device__ __forceinline__ uint32_t pack_h2(float lo, float hi) {
    uint32_t r;
    asm("cvt.rn.f16x2.f32 %0, %1, %2;" : "=r"(r) : "f"(hi), "f"(lo));
    return r;
}
__device__ __forceinline__ void splitH2(float2 v, uint32_t& hi, uint32_t& lo) {
    __half h0 = __float2half_rn(v.x);
    __half h1 = __float2half_rn(v.y);
    float r0 = v.x - __half2float(h0);
    float r1 = v.y - __half2float(h1);
    hi = (uint32_t)__half_as_ushort(h0) | ((uint32_t)__half_as_ushort(h1) << 16);
    lo = pack_h2(r0, r1);
}
__device__ __forceinline__ uint32_t panel_u32(uint32_t panel, int r, int cp) {
    int cl = cp >> 2;
    return panel * 4096u + (uint32_t)(r * 32 + ((cl ^ (r & 7)) << 2) + (cp & 3));
}

__device__ __forceinline__ void bulk_cp(uint32_t dst, const void* src, uint32_t bytes, uint32_t mbar) {
    asm volatile("cp.async.bulk.shared::cta.global.mbarrier::complete_tx::bytes [%0], [%1], %2, [%3];"
        :: "r"(dst), "l"(src), "r"(bytes), "r"(mbar) : "memory");
}
#define MBARRIER_INIT(mbar, count) \
    asm volatile("mbarrier.init.shared.b64 [%0], %1;" \
        :: "r"((uint32_t)(mbar)), "r"((uint32_t)(count)) : "memory")
#define MBARRIER_EXPECT_TX(mbar, bytes) \
    asm volatile("mbarrier.arrive.expect_tx.shared.b64 _, [%0], %1;" \
        :: "r"((uint32_t)(mbar)), "r"((uint32_t)(bytes)) : "memory")
#define MBARRIER_ARRIVE(mbar) \
    asm volatile("mbarrier.arrive.shared.b64 _, [%0];" \
        :: "r"((uint32_t)(mbar)) : "memory")
#define MBARRIER_WAIT(mbar_addr, parity) do { \
    uint32_t _mbar = (uint32_t)(mbar_addr); \
    uint32_t _par = (uint32_t)(parity); \
    uint32_t _done; \
    asm volatile("{\n\t.reg .pred p;\n\t" \
        "mbarrier.try_wait.parity.acquire.cta.shared::cta.b64 p, [%1], %2;\n\t" \
        "selp.b32 %0, 1, 0, p;\n\t}" : "=r"(_done) : "r"(_mbar), "r"(_par) : "memory"); \
    if (!_done) { \
        asm volatile("{\n\t.reg .pred P1;\n\t" \
            "WAIT_LOOP_%=:\n\t" \
            "mbarrier.try_wait.parity.acquire.cta.shared::cta.b64 P1, [%0], %1, 0x989680;\n\t" \
            "@P1 bra.uni WAIT_DONE_%=;\n\t" \
            "bra.uni WAIT_LOOP_%=;\n\t" \
            "WAIT_DONE_%=:\n\t}" :: "r"(_mbar), "r"(_par) : "memory"); \
    } \
} while(0)

__device__ __forceinline__ void ldsm4(uint32_t* r, uint32_t addr) {
    asm volatile("ldmatrix.sync.aligned.m8n8.x4.shared.b16 {%0,%1,%2,%3}, [%4];"
        : "=r"(r[0]), "=r"(r[1]), "=r"(r[2]), "=r"(r[3]) : "r"(addr));
}
__device__ __forceinline__ void ldsm4t(uint32_t* r, uint32_t addr) {
    asm volatile("ldmatrix.sync.aligned.m8n8.x4.trans.shared.b16 {%0,%1,%2,%3}, [%4];"
        : "=r"(r[0]), "=r"(r[1]), "=r"(r[2]), "=r"(r[3]) : "r"(addr));
}
__device__ __forceinline__ void mma16816h(float* c, const uint32_t* a, uint32_t b0, uint32_t b1) {
    asm volatile("mma.sync.aligned.m16n8k16.row.col.f32.f16.f16.f32 "
        "{%0,%1,%2,%3}, {%4,%5,%6,%7}, {%8,%9}, {%0,%1,%2,%3};"
        : "+f"(c[0]), "+f"(c[1]), "+f"(c[2]), "+f"(c[3])
        : "r"(a[0]), "r"(a[1]), "r"(a[2]), "r"(a[3]), "r"(b0), "r"(b1));
}

// ================= split / pack into panel layout =================
__global__ void split_f16_panel(const float* __restrict__ src, uint32_t* __restrict__ hi,
                                uint32_t* __restrict__ lo, int npairs) {
    int i = blockIdx.x * blockDim.x + threadIdx.x;
    if (i < npairs) {
        float2 v = ((const float2*)src)[i];
        uint32_t h, l;
        splitH2(v, h, l);
        int row = i >> 9, cp = i & 511;
        uint32_t idx = panel_u32((uint32_t)((row >> 7) * 16 + (cp >> 5)), row & 127, cp & 31);
        hi[idx] = h;
        lo[idx] = l;
    }
}
__global__ void pack_f16_panel(const float* __restrict__ src, uint32_t* __restrict__ dst, int npairs) {
    int i = blockIdx.x * blockDim.x + threadIdx.x;
    if (i < npairs) {
        float2 v = ((const float2*)src)[i];
        int row = i >> 9, cp = i & 511;
        uint32_t idx = panel_u32((uint32_t)((row >> 7) * 16 + (cp >> 5)), row & 127, cp & 31);
        dst[idx] = pack_h2(v.x, v.y);
    }
}

// ================= fp16 GEMM, 128x128 tile, 512 threads, 4-stage bulk pipeline =================
// warp grid 8m x 2n; warp tile 16m x 64n. De-skewed: per-stage empty barriers, no syncthreads.
// ALO: A has a lo plane (2 chains); else single chain.
template<bool FUSE_QKV, bool ALO>
__global__ __launch_bounds__(512, 1) void gemm_f16x2(
        const uint32_t* __restrict__ Ahi, const uint32_t* __restrict__ Alo,
        const uint32_t* __restrict__ Bh, float* __restrict__ C, int N,
        const float* __restrict__ qw, const float* __restrict__ kw) {
    extern __shared__ char smc[];
    const uint32_t sb = smem_to_u32(smc);
    constexpr uint32_t STAGE = ALO ? 49152u : 32768u;
    const uint32_t FB = sb + 4 * STAGE;        // 4 full barriers
    const uint32_t EB = FB + 32;               // 4 empty barriers
    const int tid = threadIdx.x;
    const int wid = tid >> 5, lane = tid & 31;
    const int wm = wid >> 1, wn = wid & 1;
    const int mt = blockIdx.y, nt = blockIdx.x;

    if (tid == 0) {
        #pragma unroll
        for (int s = 0; s < 4; s++) { MBARRIER_INIT(FB + s * 8, 1); MBARRIER_INIT(EB + s * 8, 512); }
    }
    __syncthreads();

    auto issue = [&](int s, int kt) {
        MBARRIER_EXPECT_TX(FB + s * 8, STAGE);
        bulk_cp(sb + s * STAGE, Ahi + (size_t)(mt * 16 + kt) * 4096, 16384, FB + s * 8);
        if (ALO)
            bulk_cp(sb + s * STAGE + 16384u, Alo + (size_t)(mt * 16 + kt) * 4096, 16384, FB + s * 8);
        bulk_cp(sb + s * STAGE + (ALO ? 32768u : 16384u),
                Bh + (size_t)(nt * 16 + kt) * 4096, 16384, FB + s * 8);
    };
    if (tid == 0) { issue(0, 0); issue(1, 1); issue(2, 2); issue(3, 3); }

    float acc[8][4];
    #pragma unroll
    for (int j = 0; j < 8; j++)
        #pragma unroll
        for (int e = 0; e < 4; e++) acc[j][e] = 0.0f;

    const int lrow = lane & 15, khalf = lane >> 4;

    for (int kt = 0; kt < 16; kt++) {
        const int s = kt & 3, ph = (kt >> 2) & 1;
        MBARRIER_WAIT(FB + s * 8, ph);
        const uint32_t base = sb + (uint32_t)s * STAGE;
        const uint32_t aHi = base;
        const uint32_t aLo = base + 16384u;
        const uint32_t bH  = base + (ALO ? 32768u : 16384u);

        #pragma unroll
        for (int ks = 0; ks < 4; ks++) {
            const int c = ks * 2 + khalf;
            uint32_t ah[4], al[4];
            {
                int r = wm * 16 + lrow;
                uint32_t off = (uint32_t)(r * 128 + ((c ^ (r & 7)) << 4));
                ldsm4(ah, aHi + off);
                if (ALO) ldsm4(al, aLo + off);
            }
            #pragma unroll
            for (int nb = 0; nb < 4; nb++) {
                int r = wn * 64 + nb * 16 + lrow;
                uint32_t off = (uint32_t)(r * 128 + ((c ^ (r & 7)) << 4));
                uint32_t bh[4];
                ldsm4(bh, bH + off);
                mma16816h(acc[nb * 2],     ah, bh[0], bh[2]);
                if (ALO) mma16816h(acc[nb * 2], al, bh[0], bh[2]);
                mma16816h(acc[nb * 2 + 1], ah, bh[1], bh[3]);
                if (ALO) mma16816h(acc[nb * 2 + 1], al, bh[1], bh[3]);
            }
        }
        MBARRIER_ARRIVE(EB + s * 8);
        if (tid == 0 && kt + 4 < 16) {
            MBARRIER_WAIT(EB + s * 8, ph);     // all 512 done with stage s
            issue(s, kt + 4);
        }
    }

    const int crow = lane >> 2, ccl = lane & 3;

    if (!FUSE_QKV) {
        const int ccol = ccl * 2;
        #pragma unroll
        for (int na = 0; na < 8; na++) {
            int r = mt * 128 + wm * 16 + crow;
            int cc = nt * 128 + wn * 64 + na * 8 + ccol;
            *(float2*)&C[(size_t)r * N + cc]       = make_float2(acc[na][0], acc[na][1]);
            *(float2*)&C[(size_t)(r + 8) * N + cc] = make_float2(acc[na][2], acc[na][3]);
        }
        return;
    }

    // ---------- fused RMSNorm + RoPE + fp16 panel epilogue ----------
    const int slot = nt * 2 + wn;      // one full head per warp

    if (slot >= NH + NKV) {            // V panels
        const int hv = slot - NH - NKV;
        #pragma unroll
        for (int rr = 0; rr < 2; rr++) {
            const int row = mt * 128 + wm * 16 + rr * 8 + crow;
            const int b = row >> 11, t = row & (SEQ - 1);
            const uint32_t pan = (uint32_t)((b * NKV + hv) * 16 + (t >> 7));
            const int r = t & 127;
            #pragma unroll
            for (int na = 0; na < 8; na++)
                g_vh[panel_u32(pan, r, na * 4 + ccl)] = pack_h2(acc[na][rr * 2], acc[na][rr * 2 + 1]);
        }
        return;
    }

    const bool isQ = (slot < NH);
    const float* w = isQ ? qw : kw;
    float w0[8], w1[8], invf[8];
    #pragma unroll
    for (int na = 0; na < 8; na++) {
        const int i = na * 4 + ccl;
        w0[na] = w[2 * i];
        w1[na] = w[2 * i + 1];
        invf[na] = __powf(10000.0f, -(float)(2 * i) / (float)DK);
    }
    const float qs = 0.125f * 1.4426950408889634f;

    #pragma unroll
    for (int rr = 0; rr < 2; rr++) {
        const int row = mt * 128 + wm * 16 + rr * 8 + crow;
        const int b = row >> 11, t = row & (SEQ - 1);

        float ss = 0.0f;
        #pragma unroll
        for (int na = 0; na < 8; na++) {
            float v0 = acc[na][rr * 2], v1 = acc[na][rr * 2 + 1];
            ss += v0 * v0 + v1 * v1;
        }
        ss += __shfl_xor_sync(0xffffffffu, ss, 1);
        ss += __shfl_xor_sync(0xffffffffu, ss, 2);
        const float rnorm = rsqrtf(ss * (1.0f / DK) + 1.1920929e-07f);

        const uint32_t pan = isQ
            ? (uint32_t)((b * NH + slot) * 16 + (t >> 7))
            : (uint32_t)((b * NKV + (slot - NH)) * 16 + (t >> 7));
        const int r = t & 127;

        #pragma unroll
        for (int na = 0; na < 8; na++) {
            float y0 = acc[na][rr * 2]     * rnorm * w0[na];
            float y1 = acc[na][rr * 2 + 1] * rnorm * w1[na];
            float sv, cv;
            sincosf((float)t * invf[na], &sv, &cv);
            float o0 = y0 * cv - y1 * sv;
            float o1 = y0 * sv + y1 * cv;
            if (isQ) g_qh[panel_u32(pan, r, na * 4 + ccl)] = pack_h2(o0 * qs, o1 * qs);
            else     g_kh[panel_u32(pan, r, na * 4 + ccl)] = pack_h2(o0, o1);
        }
    }
}

// ================= tensor-core causal flash attention, 256 threads, 3-stage de-skewed =================
// warp grid 4(q) x 2(kv): warp = 32 q-rows x 64 kv-cols. Q/K/V single fp16.
// smem: KV stages @0/32768/65536, Q @98304, FBs @114688, EBs @114720.
__global__ __launch_bounds__(256, 1) void attn_mma() {
    extern __shared__ char sma[];
    const uint32_t sb = smem_to_u32(sma);
    const uint32_t FB = sb + 114688u;
    const uint32_t EB = FB + 32u;
    const int tid = threadIdx.x;
    const int wid = tid >> 5, lane = tid & 31;
    const int wq = wid >> 1, wk = wid & 1;
    const int qb = (int)gridDim.x - 1 - (int)blockIdx.x;
    const int h  = blockIdx.y, b = blockIdx.z;
    const int kvh = h / GROUPS;
    const int nkb = qb + 1;

    if (tid == 0) {
        #pragma unroll
        for (int s = 0; s < 3; s++) { MBARRIER_INIT(FB + s * 8, 1); MBARRIER_INIT(EB + s * 8, 256); }
        MBARRIER_INIT(FB + 24, 1);   // Q barrier
    }
    __syncthreads();

    const uint32_t qpan  = (uint32_t)((b * NH + h) * 16 + qb);
    const uint32_t kvpan = (uint32_t)((b * NKV + kvh) * 16);

    auto issue = [&](int s, int kb) {
        MBARRIER_EXPECT_TX(FB + s * 8, 32768);
        bulk_cp(sb + s * 32768u,          g_kh + (size_t)(kvpan + kb) * 4096, 16384, FB + s * 8);
        bulk_cp(sb + s * 32768u + 16384u, g_vh + (size_t)(kvpan + kb) * 4096, 16384, FB + s * 8);
    };
    if (tid == 0) {
        MBARRIER_EXPECT_TX(FB + 24, 16384);
        bulk_cp(sb + 98304u, g_qh + (size_t)qpan * 4096, 16384, FB + 24);
        issue(0, 0);
        if (nkb > 1) issue(1, 1);
        if (nkb > 2) issue(2, 2);
    }

    MBARRIER_WAIT(FB + 24, 0);
    const int lrow = lane & 15, khalf = lane >> 4;
    uint32_t qh[2][4][4];
    #pragma unroll
    for (int rb = 0; rb < 2; rb++) {
        const int r = wq * 32 + rb * 16 + lrow;
        #pragma unroll
        for (int ks = 0; ks < 4; ks++) {
            const int c = ks * 2 + khalf;
            uint32_t off = (uint32_t)(r * 128 + ((c ^ (r & 7)) << 4));
            ldsm4(qh[rb][ks], sb + 98304u + off);
        }
    }

    float oa[2][8][4];
    #pragma unroll
    for (int rb = 0; rb < 2; rb++)
        #pragma unroll
        for (int j = 0; j < 8; j++)
            #pragma unroll
            for (int e = 0; e < 4; e++) oa[rb][j][e] = 0.0f;
    float lsum[2][2] = {{0.0f, 0.0f}, {0.0f, 0.0f}};

    const int vrow_base = ((lane >> 3) & 1) * 8 + (lane & 7);
    const int vkh = lane >> 4;

    int st = 0, ph = 0;   // stage, phase over modulo-3 ring
    for (int kb = 0; kb < nkb; kb++) {
        MBARRIER_WAIT(FB + st * 8, ph);
        const uint32_t kH = sb + (uint32_t)st * 32768u;
        const uint32_t vH = kH + 16384u;

        float sc[2][8][4];
        #pragma unroll
        for (int rb = 0; rb < 2; rb++)
            #pragma unroll
            for (int j = 0; j < 8; j++)
                #pragma unroll
                for (int e = 0; e < 4; e++) sc[rb][j][e] = 0.0f;

        #pragma unroll
        for (int ks = 0; ks < 4; ks++) {
            const int c = ks * 2 + khalf;
            #pragma unroll
            for (int nb = 0; nb < 4; nb++) {
                int r = wk * 64 + nb * 16 + lrow;
                uint32_t off = (uint32_t)(r * 128 + ((c ^ (r & 7)) << 4));
                uint32_t kh[4];
                ldsm4(kh, kH + off);
                #pragma unroll
                for (int rb = 0; rb < 2; rb++) {
                    mma16816h(sc[rb][2 * nb],     qh[rb][ks], kh[0], kh[2]);
                    mma16816h(sc[rb][2 * nb + 1], qh[rb][ks], kh[1], kh[3]);
                }
            }
        }

        if (kb == qb) {
            #pragma unroll
            for (int rb = 0; rb < 2; rb++) {
                const int g0 = qb * 128 + wq * 32 + rb * 16 + (lane >> 2);
                const int g1 = g0 + 8;
                #pragma unroll
                for (int j = 0; j < 8; j++) {
                    const int c0 = kb * 128 + wk * 64 + 8 * j + (lane & 3) * 2;
                    const int c1 = c0 + 1;
                    if (c0 > g0) sc[rb][j][0] = -INFINITY;
                    if (c1 > g0) sc[rb][j][1] = -INFINITY;
                    if (c0 > g1) sc[rb][j][2] = -INFINITY;
                    if (c1 > g1) sc[rb][j][3] = -INFINITY;
                }
            }
        }

        #pragma unroll
        for (int rb = 0; rb < 2; rb++) {
            #pragma unroll
            for (int j = 0; j < 8; j++) {
                sc[rb][j][0] = ex2(sc[rb][j][0]);
                sc[rb][j][1] = ex2(sc[rb][j][1]);
                sc[rb][j][2] = ex2(sc[rb][j][2]);
                sc[rb][j][3] = ex2(sc[rb][j][3]);
                lsum[rb][0] += sc[rb][j][0] + sc[rb][j][1];
                lsum[rb][1] += sc[rb][j][2] + sc[rb][j][3];
            }
        }

        uint32_t pa[2][4][4];
        #pragma unroll
        for (int rb = 0; rb < 2; rb++)
            #pragma unroll
            for (int kk = 0; kk < 4; kk++) {
                pa[rb][kk][0] = pack_h2(sc[rb][2 * kk][0],     sc[rb][2 * kk][1]);
                pa[rb][kk][1] = pack_h2(sc[rb][2 * kk][2],     sc[rb][2 * kk][3]);
                pa[rb][kk][2] = pack_h2(sc[rb][2 * kk + 1][0], sc[rb][2 * kk + 1][1]);
                pa[rb][kk][3] = pack_h2(sc[rb][2 * kk + 1][2], sc[rb][2 * kk + 1][3]);
            }

        #pragma unroll
        for (int kk = 0; kk < 4; kk++) {
            const int vr = wk * 64 + kk * 16 + vrow_base;
            #pragma unroll
            for (int ng = 0; ng < 4; ng++) {
                const int vc = ng * 2 + vkh;
                uint32_t off = (uint32_t)(vr * 128 + ((vc ^ (vr & 7)) << 4));
                uint32_t vh[4];
                ldsm4t(vh, vH + off);
                #pragma unroll
                for (int rb = 0; rb < 2; rb++) {
                    mma16816h(oa[rb][2 * ng],     pa[rb][kk], vh[0], vh[1]);
                    mma16816h(oa[rb][2 * ng + 1], pa[rb][kk], vh[2], vh[3]);
                }
            }
        }

        MBARRIER_ARRIVE(EB + st * 8);
        if (tid == 0 && kb + 3 < nkb) {
            MBARRIER_WAIT(EB + st * 8, ph);
            issue(st, kb + 3);
        }
        st++;
        if (st == 3) { st = 0; ph ^= 1; }
    }

    // ---- quad-reduce l, combine kv-half partials via smem ----
    #pragma unroll
    for (int rb = 0; rb < 2; rb++) {
        lsum[rb][0] += __shfl_xor_sync(0xffffffffu, lsum[rb][0], 1);
        lsum[rb][0] += __shfl_xor_sync(0xffffffffu, lsum[rb][0], 2);
        lsum[rb][1] += __shfl_xor_sync(0xffffffffu, lsum[rb][1], 1);
        lsum[rb][1] += __shfl_xor_sync(0xffffffffu, lsum[rb][1], 2);
    }

    float* xch = (float*)sma;
    __syncthreads();
    if (wk == 1) {
        float* dst = xch + (wq * 32 + lane) * 68;
        #pragma unroll
        for (int rb = 0; rb < 2; rb++)
            #pragma unroll
            for (int j = 0; j < 8; j++) {
                dst[rb * 32 + j * 4 + 0] = oa[rb][j][0];
                dst[rb * 32 + j * 4 + 1] = oa[rb][j][1];
                dst[rb * 32 + j * 4 + 2] = oa[rb][j][2];
                dst[rb * 32 + j * 4 + 3] = oa[rb][j][3];
            }
        dst[64] = lsum[0][0]; dst[65] = lsum[0][1];
        dst[66] = lsum[1][0]; dst[67] = lsum[1][1];
    }
    __syncthreads();
    if (wk == 1) return;

    {
        const float* src = xch + (wq * 32 + lane) * 68;
        #pragma unroll
        for (int rb = 0; rb < 2; rb++)
            #pragma unroll
            for (int j = 0; j < 8; j++) {
                oa[rb][j][0] += src[rb * 32 + j * 4 + 0];
                oa[rb][j][1] += src[rb * 32 + j * 4 + 1];
                oa[rb][j][2] += src[rb * 32 + j * 4 + 2];
                oa[rb][j][3] += src[rb * 32 + j * 4 + 3];
            }
        lsum[0][0] += src[64]; lsum[0][1] += src[65];
        lsum[1][0] += src[66]; lsum[1][1] += src[67];
    }

    #pragma unroll
    for (int rb = 0; rb < 2; rb++) {
        const float inv0 = 1.0f / lsum[rb][0], inv1 = 1.0f / lsum[rb][1];
        const int t0 = qb * 128 + wq * 32 + rb * 16 + (lane >> 2);
        const int t1 = t0 + 8;
        const uint32_t pan = (uint32_t)((b * 16 + qb) * 16 + h);
        const int r0 = t0 & 127, r1 = t1 & 127;
        #pragma unroll
        for (int j = 0; j < 8; j++) {
            const int cp = j * 4 + (lane & 3);
            g_ah[panel_u32(pan, r0, cp)] = pack_h2(oa[rb][j][0] * inv0, oa[rb][j][1] * inv0);
            g_ah[panel_u32(pan, r1, cp)] = pack_h2(oa[rb][j][2] * inv1, oa[rb][j][3] * inv1);
        }
    }
}

// ================= launch =================
extern "C" void kernel_launch(void* const* d_in, const int* in_sizes, int n_in,
                              void* d_out, int out_size) {
    const float* x    = (const float*)d_in[0];
    const float* qkvo = (const float*)d_in[1];
    const float* qw   = (const float*)d_in[2];
    const float* kw   = (const float*)d_in[3];
    float* out = (float*)d_out;

    void *p_xhi, *p_xlo, *p_wh, *p_ah;
    cudaGetSymbolAddress(&p_xhi, g_xhi); cudaGetSymbolAddress(&p_xlo, g_xlo);
    cudaGetSymbolAddress(&p_wh, g_wh);
    cudaGetSymbolAddress(&p_ah, g_ah);

    const int GEMM1_SMEM = 4 * 49152 + 128;   // ALO=true
    const int GEMM2_SMEM = 4 * 32768 + 128;   // ALO=false
    const int ATTN_SMEM  = 114688 + 128;
    cudaFuncSetAttribute((const void*)gemm_f16x2<true, true>,   cudaFuncAttributeMaxDynamicSharedMemorySize, GEMM1_SMEM);
    cudaFuncSetAttribute((const void*)gemm_f16x2<false, false>, cudaFuncAttributeMaxDynamicSharedMemorySize, GEMM2_SMEM);
    cudaFuncSetAttribute((const void*)attn_mma, cudaFuncAttributeMaxDynamicSharedMemorySize, ATTN_SMEM);

    // 0) split x (hi/lo) and pack weights into panel layout
    {
        int np = ROWS * GK / 2;
        split_f16_panel<<<np / 256, 256>>>(x, (uint32_t*)p_xhi, (uint32_t*)p_xlo, np);
        int nw = 2560 * GK / 2;
        pack_f16_panel<<<nw / 256, 256>>>(qkvo, (uint32_t*)p_wh, nw);
    }

    // 1) QKV projection + fused RMSNorm/RoPE -> Q/K/V fp16 panels
    gemm_f16x2<true, true><<<dim3(QKVN / 128, ROWS / 128), 512, GEMM1_SMEM>>>(
        (const uint32_t*)p_xhi, (const uint32_t*)p_xlo,
        (const uint32_t*)p_wh, nullptr, QKVN, qw, kw);

    // 2) tensor-core causal flash attention -> g_ah panels (single fp16)
    attn_mma<<<dim3(SEQ / 128, NH, BATCH), 256, ATTN_SMEM>>>();

    // 3) O projection (A single plane; weights panels start at nt=12)
    gemm_f16x2<false, false><<<dim3(DM / 128, ROWS / 128), 512, GEMM2_SMEM>>>(
        (const uint32_t*)p_ah, nullptr,
        (const uint32_t*)p_wh + (size_t)12 * 16 * 4096, out, DM, nullptr, nullptr);
}

// round 16
// speedup vs baseline: 1.2652x; 1.0304x over previous
#include <cuda_runtime.h>
#include <cuda_fp16.h>
#include <math.h>
#include <stdint.h>

#define BATCH 2
#define SEQ   2048
#define DM    1024
#define NH    16
#define NKV   4
#define DK    64
#define QKVN  1536
#define ROWS  (BATCH*SEQ)
#define GROUPS (NH/NKV)
#define GK    1024

// ---------------- scratch: pre-swizzled 16KB panels (128 rows x 64 fp16 cols) ----------------
__device__ __align__(128) uint32_t g_xhi[ROWS * GK / 2],  g_xlo[ROWS * GK / 2];
__device__ __align__(128) uint32_t g_wh [2560 * GK / 2];
__device__ __align__(128) uint32_t g_ah [ROWS * DM / 2];            // attn out single fp16
__device__ __align__(128) uint32_t g_qh [BATCH * NH  * SEQ * DK / 2];
__device__ __align__(128) uint32_t g_kh [BATCH * NKV * SEQ * DK / 2];
__device__ __align__(128) uint32_t g_vh [BATCH * NKV * SEQ * DK / 2];
__device__ __align__(16)  float2   g_rope[SEQ * 32];                // (cos,sin) per (t, pair)

// ================= helpers =================
__device__ __forceinline__ uint32_t smem_to_u32(const void* p) {
    uint32_t a;
    asm("{ .reg .u64 t; cvta.to.shared.u64 t, %1; cvt.u32.u64 %0, t; }" : "=r"(a) : "l"(p));
    return a;
}
__device__ __forceinline__ float ex2(float x) {
    float r; asm("ex2.approx.f32 %0, %1;" : "=f"(r) : "f"(x)); return r;
}
__device__ __forceinline__ uint32_t pack_h2(float lo, float hi) {
    uint32_t r;
    asm("cvt.rn.f16x2.f32 %0, %1, %2;" : "=r"(r) : "f"(hi), "f"(lo));
    return r;
}
__device__ __forceinline__ void splitH2(float2 v, uint32_t& hi, uint32_t& lo) {
    __half h0 = __float2half_rn(v.x);
    __half h1 = __float2half_rn(v.y);
    float r0 = v.x - __half2float(h0);
    float r1 = v.y - __half2float(h1);
    hi = (uint32_t)__half_as_ushort(h0) | ((uint32_t)__half_as_ushort(h1) << 16);
    lo = pack_h2(r0, r1);
}
__device__ __forceinline__ uint32_t panel_u32(uint32_t panel, int r, int cp) {
    int cl = cp >> 2;
    return panel * 4096u + (uint32_t)(r * 32 + ((cl ^ (r & 7)) << 2) + (cp & 3));
}

__device__ __forceinline__ void bulk_cp(uint32_t dst, const void* src, uint32_t bytes, uint32_t mbar) {
    asm volatile("cp.async.bulk.shared::cta.global.mbarrier::complete_tx::bytes [%0], [%1], %2, [%3];"
        :: "r"(dst), "l"(src), "r"(bytes), "r"(mbar) : "memory");
}
#define MBARRIER_INIT(mbar, count) \
    asm volatile("mbarrier.init.shared.b64 [%0], %1;" \
        :: "r"((uint32_t)(mbar)), "r"((uint32_t)(count)) : "memory")
#define MBARRIER_EXPECT_TX(mbar, bytes) \
    asm volatile("mbarrier.arrive.expect_tx.shared.b64 _, [%0], %1;" \
        :: "r"((uint32_t)(mbar)), "r"((uint32_t)(bytes)) : "memory")
#define MBARRIER_ARRIVE(mbar) \
    asm volatile("mbarrier.arrive.shared.b64 _, [%0];" \
        :: "r"((uint32_t)(mbar)) : "memory")
#define MBARRIER_WAIT(mbar_addr, parity) do { \
    uint32_t _mbar = (uint32_t)(mbar_addr); \
    uint32_t _par = (uint32_t)(parity); \
    uint32_t _done; \
    asm volatile("{\n\t.reg .pred p;\n\t" \
        "mbarrier.try_wait.parity.acquire.cta.shared::cta.b64 p, [%1], %2;\n\t" \
        "selp.b32 %0, 1, 0, p;\n\t}" : "=r"(_done) : "r"(_mbar), "r"(_par) : "memory"); \
    if (!_done) { \
        asm volatile("{\n\t.reg .pred P1;\n\t" \
            "WAIT_LOOP_%=:\n\t" \
            "mbarrier.try_wait.parity.acquire.cta.shared::cta.b64 P1, [%0], %1, 0x989680;\n\t" \
            "@P1 bra.uni WAIT_DONE_%=;\n\t" \
            "bra.uni WAIT_LOOP_%=;\n\t" \
            "WAIT_DONE_%=:\n\t}" :: "r"(_mbar), "r"(_par) : "memory"); \
    } \
} while(0)

__device__ __forceinline__ void ldsm4(uint32_t* r, uint32_t addr) {
    asm volatile("ldmatrix.sync.aligned.m8n8.x4.shared.b16 {%0,%1,%2,%3}, [%4];"
        : "=r"(r[0]), "=r"(r[1]), "=r"(r[2]), "=r"(r[3]) : "r"(addr));
}
__device__ __forceinline__ void ldsm4t(uint32_t* r, uint32_t addr) {
    asm volatile("ldmatrix.sync.aligned.m8n8.x4.trans.shared.b16 {%0,%1,%2,%3}, [%4];"
        : "=r"(r[0]), "=r"(r[1]), "=r"(r[2]), "=r"(r[3]) : "r"(addr));
}
__device__ __forceinline__ void mma16816h(float* c, const uint32_t* a, uint32_t b0, uint32_t b1) {
    asm volatile("mma.sync.aligned.m16n8k16.row.col.f32.f16.f16.f32 "
        "{%0,%1,%2,%3}, {%4,%5,%6,%7}, {%8,%9}, {%0,%1,%2,%3};"
        : "+f"(c[0]), "+f"(c[1]), "+f"(c[2]), "+f"(c[3])
        : "r"(a[0]), "r"(a[1]), "r"(a[2]), "r"(a[3]), "r"(b0), "r"(b1));
}

// ================= fused prep: x split + w pack + RoPE table =================
#define XG 524288   // x groups of 4 pairs
#define WG 327680   // w groups of 4 pairs
__global__ void prep_all(const float* __restrict__ x, const float* __restrict__ wsrc,
                         const float* __restrict__ qw_unused) {
    int i = blockIdx.x * blockDim.x + threadIdx.x;
    if (i < XG) {
        int row = i >> 7, cp0 = (i & 127) * 4;
        const float4* s = (const float4*)(x + (size_t)row * 1024 + cp0 * 2);
        float4 a = s[0], b = s[1];
        uint32_t h0, h1, h2, h3, l0, l1, l2, l3;
        splitH2(make_float2(a.x, a.y), h0, l0);
        splitH2(make_float2(a.z, a.w), h1, l1);
        splitH2(make_float2(b.x, b.y), h2, l2);
        splitH2(make_float2(b.z, b.w), h3, l3);
        uint32_t idx = panel_u32((uint32_t)((row >> 7) * 16 + (cp0 >> 5)), row & 127, cp0 & 31);
        *(uint4*)&g_xhi[idx] = make_uint4(h0, h1, h2, h3);
        *(uint4*)&g_xlo[idx] = make_uint4(l0, l1, l2, l3);
    } else if (i < XG + WG) {
        int g = i - XG;
        int row = g >> 7, cp0 = (g & 127) * 4;
        const float4* s = (const float4*)(wsrc + (size_t)row * 1024 + cp0 * 2);
        float4 a = s[0], b = s[1];
        uint32_t idx = panel_u32((uint32_t)((row >> 7) * 16 + (cp0 >> 5)), row & 127, cp0 & 31);
        *(uint4*)&g_wh[idx] = make_uint4(pack_h2(a.x, a.y), pack_h2(a.z, a.w),
                                         pack_h2(b.x, b.y), pack_h2(b.z, b.w));
    } else {
        int e = i - XG - WG;                 // < 65536
        int t = e >> 5, li = e & 31;
        float invf = __powf(10000.0f, -(float)(2 * li) / (float)DK);
        float sv, cv;
        sincosf((float)t * invf, &sv, &cv);
        g_rope[t * 32 + li] = make_float2(cv, sv);
    }
}

// ================= persistent fp16 GEMM, 128x128 tiles, 512 threads, 4-stage bulk =================
// warp grid 8m x 2n; warp tile 16m x 64n. De-skewed stage barriers continue across tiles.
template<bool FUSE_QKV, bool ALO>
__global__ __launch_bounds__(512, 1) void gemm_f16x2(
        const uint32_t* __restrict__ Ahi, const uint32_t* __restrict__ Alo,
        const uint32_t* __restrict__ Bh, float* __restrict__ C, int N,
        const float* __restrict__ qw, const float* __restrict__ kw,
        int NT, int NTILES) {
    extern __shared__ char smc[];
    const uint32_t sb = smem_to_u32(smc);
    constexpr uint32_t STAGE = ALO ? 49152u : 32768u;
    const uint32_t FB = sb + 4 * STAGE;
    const uint32_t EB = FB + 32;
    const int tid = threadIdx.x;
    const int wid = tid >> 5, lane = tid & 31;
    const int wm = wid >> 1, wn = wid & 1;

    if (tid == 0) {
        #pragma unroll
        for (int s = 0; s < 4; s++) { MBARRIER_INIT(FB + s * 8, 1); MBARRIER_INIT(EB + s * 8, 512); }
    }
    __syncthreads();

    auto issue_kg = [&](int kg) {
        int tile = blockIdx.x + (kg >> 4) * gridDim.x;
        if (tile >= NTILES) return;
        int kt = kg & 15;
        int mt = tile / NT, nt = tile % NT;
        int s = kg & 3;
        MBARRIER_EXPECT_TX(FB + s * 8, STAGE);
        bulk_cp(sb + s * STAGE, Ahi + (size_t)(mt * 16 + kt) * 4096, 16384, FB + s * 8);
        if (ALO)
            bulk_cp(sb + s * STAGE + 16384u, Alo + (size_t)(mt * 16 + kt) * 4096, 16384, FB + s * 8);
        bulk_cp(sb + s * STAGE + (ALO ? 32768u : 16384u),
                Bh + (size_t)(nt * 16 + kt) * 4096, 16384, FB + s * 8);
    };
    if (tid == 0) { issue_kg(0); issue_kg(1); issue_kg(2); issue_kg(3); }

    const int lrow = lane & 15, khalf = lane >> 4;
    const int crow = lane >> 2, ccl = lane & 3;

    float w0[8], w1[8];
    if (FUSE_QKV) {
        // weights for Q/K loaded lazily per slot in epilogue (slot varies per tile)
    }

    int tl = 0;
    for (int tile = blockIdx.x; tile < NTILES; tile += gridDim.x, tl++) {
        const int mt = tile / NT, nt = tile % NT;

        float acc[8][4];
        #pragma unroll
        for (int j = 0; j < 8; j++)
            #pragma unroll
            for (int e = 0; e < 4; e++) acc[j][e] = 0.0f;

        for (int kt = 0; kt < 16; kt++) {
            const int kg = tl * 16 + kt;
            const int s = kg & 3, ph = (kg >> 2) & 1;
            MBARRIER_WAIT(FB + s * 8, ph);
            const uint32_t base = sb + (uint32_t)s * STAGE;
            const uint32_t aHi = base;
            const uint32_t aLo = base + 16384u;
            const uint32_t bH  = base + (ALO ? 32768u : 16384u);

            #pragma unroll
            for (int ks = 0; ks < 4; ks++) {
                const int c = ks * 2 + khalf;
                uint32_t ah[4], al[4];
                {
                    int r = wm * 16 + lrow;
                    uint32_t off = (uint32_t)(r * 128 + ((c ^ (r & 7)) << 4));
                    ldsm4(ah, aHi + off);
                    if (ALO) ldsm4(al, aLo + off);
                }
                #pragma unroll
                for (int nb = 0; nb < 4; nb++) {
                    int r = wn * 64 + nb * 16 + lrow;
                    uint32_t off = (uint32_t)(r * 128 + ((c ^ (r & 7)) << 4));
                    uint32_t bh[4];
                    ldsm4(bh, bH + off);
                    mma16816h(acc[nb * 2],     ah, bh[0], bh[2]);
                    if (ALO) mma16816h(acc[nb * 2], al, bh[0], bh[2]);
                    mma16816h(acc[nb * 2 + 1], ah, bh[1], bh[3]);
                    if (ALO) mma16816h(acc[nb * 2 + 1], al, bh[1], bh[3]);
                }
            }
            MBARRIER_ARRIVE(EB + s * 8);
            if (tid == 0) {
                MBARRIER_WAIT(EB + s * 8, ph);
                issue_kg(kg + 4);
            }
        }

        if (!FUSE_QKV) {
            const int ccol = ccl * 2;
            #pragma unroll
            for (int na = 0; na < 8; na++) {
                int r = mt * 128 + wm * 16 + crow;
                int cc = nt * 128 + wn * 64 + na * 8 + ccol;
                *(float2*)&C[(size_t)r * N + cc]       = make_float2(acc[na][0], acc[na][1]);
                *(float2*)&C[(size_t)(r + 8) * N + cc] = make_float2(acc[na][2], acc[na][3]);
            }
            continue;
        }

        // ---------- fused RMSNorm + RoPE(table) + fp16 panel epilogue ----------
        const int slot = nt * 2 + wn;

        if (slot >= NH + NKV) {            // V panels
            const int hv = slot - NH - NKV;
            #pragma unroll
            for (int rr = 0; rr < 2; rr++) {
                const int row = mt * 128 + wm * 16 + rr * 8 + crow;
                const int b = row >> 11, t = row & (SEQ - 1);
                const uint32_t pan = (uint32_t)((b * NKV + hv) * 16 + (t >> 7));
                const int r = t & 127;
                #pragma unroll
                for (int na = 0; na < 8; na++)
                    g_vh[panel_u32(pan, r, na * 4 + ccl)] =
                        pack_h2(acc[na][rr * 2], acc[na][rr * 2 + 1]);
            }
            continue;
        }

        const bool isQ = (slot < NH);
        const float* w = isQ ? qw : kw;
        #pragma unroll
        for (int na = 0; na < 8; na++) {
            const int i2 = na * 4 + ccl;
            w0[na] = w[2 * i2];
            w1[na] = w[2 * i2 + 1];
        }
        const float qs = 0.125f * 1.4426950408889634f;

        #pragma unroll
        for (int rr = 0; rr < 2; rr++) {
            const int row = mt * 128 + wm * 16 + rr * 8 + crow;
            const int b = row >> 11, t = row & (SEQ - 1);

            float ss = 0.0f;
            #pragma unroll
            for (int na = 0; na < 8; na++) {
                float v0 = acc[na][rr * 2], v1 = acc[na][rr * 2 + 1];
                ss += v0 * v0 + v1 * v1;
            }
            ss += __shfl_xor_sync(0xffffffffu, ss, 1);
            ss += __shfl_xor_sync(0xffffffffu, ss, 2);
            const float rnorm = rsqrtf(ss * (1.0f / DK) + 1.1920929e-07f);

            const uint32_t pan = isQ
                ? (uint32_t)((b * NH + slot) * 16 + (t >> 7))
                : (uint32_t)((b * NKV + (slot - NH)) * 16 + (t >> 7));
            const int r = t & 127;

            #pragma unroll
            for (int na = 0; na < 8; na++) {
                float y0 = acc[na][rr * 2]     * rnorm * w0[na];
                float y1 = acc[na][rr * 2 + 1] * rnorm * w1[na];
                float2 cs = g_rope[t * 32 + na * 4 + ccl];
                float o0 = y0 * cs.x - y1 * cs.y;
                float o1 = y0 * cs.y + y1 * cs.x;
                if (isQ) g_qh[panel_u32(pan, r, na * 4 + ccl)] = pack_h2(o0 * qs, o1 * qs);
                else     g_kh[panel_u32(pan, r, na * 4 + ccl)] = pack_h2(o0, o1);
            }
        }
    }
}

// ================= tensor-core causal flash attention (unchanged from R15) =================
__global__ __launch_bounds__(256, 1) void attn_mma() {
    extern __shared__ char sma[];
    const uint32_t sb = smem_to_u32(sma);
    const uint32_t FB = sb + 114688u;
    const uint32_t EB = FB + 32u;
    const int tid = threadIdx.x;
    const int wid = tid >> 5, lane = tid & 31;
    const int wq = wid >> 1, wk = wid & 1;
    const int qb = (int)gridDim.x - 1 - (int)blockIdx.x;
    const int h  = blockIdx.y, b = blockIdx.z;
    const int kvh = h / GROUPS;
    const int nkb = qb + 1;

    if (tid == 0) {
        #pragma unroll
        for (int s = 0; s < 3; s++) { MBARRIER_INIT(FB + s * 8, 1); MBARRIER_INIT(EB + s * 8, 256); }
        MBARRIER_INIT(FB + 24, 1);
    }
    __syncthreads();

    const uint32_t qpan  = (uint32_t)((b * NH + h) * 16 + qb);
    const uint32_t kvpan = (uint32_t)((b * NKV + kvh) * 16);

    auto issue = [&](int s, int kb) {
        MBARRIER_EXPECT_TX(FB + s * 8, 32768);
        bulk_cp(sb + s * 32768u,          g_kh + (size_t)(kvpan + kb) * 4096, 16384, FB + s * 8);
        bulk_cp(sb + s * 32768u + 16384u, g_vh + (size_t)(kvpan + kb) * 4096, 16384, FB + s * 8);
    };
    if (tid == 0) {
        MBARRIER_EXPECT_TX(FB + 24, 16384);
        bulk_cp(sb + 98304u, g_qh + (size_t)qpan * 4096, 16384, FB + 24);
        issue(0, 0);
        if (nkb > 1) issue(1, 1);
        if (nkb > 2) issue(2, 2);
    }

    MBARRIER_WAIT(FB + 24, 0);
    const int lrow = lane & 15, khalf = lane >> 4;
    uint32_t qh[2][4][4];
    #pragma unroll
    for (int rb = 0; rb < 2; rb++) {
        const int r = wq * 32 + rb * 16 + lrow;
        #pragma unroll
        for (int ks = 0; ks < 4; ks++) {
            const int c = ks * 2 + khalf;
            uint32_t off = (uint32_t)(r * 128 + ((c ^ (r & 7)) << 4));
            ldsm4(qh[rb][ks], sb + 98304u + off);
        }
    }

    float oa[2][8][4];
    #pragma unroll
    for (int rb = 0; rb < 2; rb++)
        #pragma unroll
        for (int j = 0; j < 8; j++)
            #pragma unroll
            for (int e = 0; e < 4; e++) oa[rb][j][e] = 0.0f;
    float lsum[2][2] = {{0.0f, 0.0f}, {0.0f, 0.0f}};

    const int vrow_base = ((lane >> 3) & 1) * 8 + (lane & 7);
    const int vkh = lane >> 4;

    int st = 0, ph = 0;
    for (int kb = 0; kb < nkb; kb++) {
        MBARRIER_WAIT(FB + st * 8, ph);
        const uint32_t kH = sb + (uint32_t)st * 32768u;
        const uint32_t vH = kH + 16384u;

        float sc[2][8][4];
        #pragma unroll
        for (int rb = 0; rb < 2; rb++)
            #pragma unroll
            for (int j = 0; j < 8; j++)
                #pragma unroll
                for (int e = 0; e < 4; e++) sc[rb][j][e] = 0.0f;

        #pragma unroll
        for (int ks = 0; ks < 4; ks++) {
            const int c = ks * 2 + khalf;
            #pragma unroll
            for (int nb = 0; nb < 4; nb++) {
                int r = wk * 64 + nb * 16 + lrow;
                uint32_t off = (uint32_t)(r * 128 + ((c ^ (r & 7)) << 4));
                uint32_t kh[4];
                ldsm4(kh, kH + off);
                #pragma unroll
                for (int rb = 0; rb < 2; rb++) {
                    mma16816h(sc[rb][2 * nb],     qh[rb][ks], kh[0], kh[2]);
                    mma16816h(sc[rb][2 * nb + 1], qh[rb][ks], kh[1], kh[3]);
                }
            }
        }

        if (kb == qb) {
            #pragma unroll
            for (int rb = 0; rb < 2; rb++) {
                const int g0 = qb * 128 + wq * 32 + rb * 16 + (lane >> 2);
                const int g1 = g0 + 8;
                #pragma unroll
                for (int j = 0; j < 8; j++) {
                    const int c0 = kb * 128 + wk * 64 + 8 * j + (lane & 3) * 2;
                    const int c1 = c0 + 1;
                    if (c0 > g0) sc[rb][j][0] = -INFINITY;
                    if (c1 > g0) sc[rb][j][1] = -INFINITY;
                    if (c0 > g1) sc[rb][j][2] = -INFINITY;
                    if (c1 > g1) sc[rb][j][3] = -INFINITY;
                }
            }
        }

        #pragma unroll
        for (int rb = 0; rb < 2; rb++) {
            #pragma unroll
            for (int j = 0; j < 8; j++) {
                sc[rb][j][0] = ex2(sc[rb][j][0]);
                sc[rb][j][1] = ex2(sc[rb][j][1]);
                sc[rb][j][2] = ex2(sc[rb][j][2]);
                sc[rb][j][3] = ex2(sc[rb][j][3]);
                lsum[rb][0] += sc[rb][j][0] + sc[rb][j][1];
                lsum[rb][1] += sc[rb][j][2] + sc[rb][j][3];
            }
        }

        uint32_t pa[2][4][4];
        #pragma unroll
        for (int rb = 0; rb < 2; rb++)
            #pragma unroll
            for (int kk = 0; kk < 4; kk++) {
                pa[rb][kk][0] = pack_h2(sc[rb][2 * kk][0],     sc[rb][2 * kk][1]);
                pa[rb][kk][1] = pack_h2(sc[rb][2 * kk][2],     sc[rb][2 * kk][3]);
                pa[rb][kk][2] = pack_h2(sc[rb][2 * kk + 1][0], sc[rb][2 * kk + 1][1]);
                pa[rb][kk][3] = pack_h2(sc[rb][2 * kk + 1][2], sc[rb][2 * kk + 1][3]);
            }

        #pragma unroll
        for (int kk = 0; kk < 4; kk++) {
            const int vr = wk * 64 + kk * 16 + vrow_base;
            #pragma unroll
            for (int ng = 0; ng < 4; ng++) {
                const int vc = ng * 2 + vkh;
                uint32_t off = (uint32_t)(vr * 128 + ((vc ^ (vr & 7)) << 4));
                uint32_t vh[4];
                ldsm4t(vh, vH + off);
                #pragma unroll
                for (int rb = 0; rb < 2; rb++) {
                    mma16816h(oa[rb][2 * ng],     pa[rb][kk], vh[0], vh[1]);
                    mma16816h(oa[rb][2 * ng + 1], pa[rb][kk], vh[2], vh[3]);
                }
            }
        }

        MBARRIER_ARRIVE(EB + st * 8);
        if (tid == 0 && kb + 3 < nkb) {
            MBARRIER_WAIT(EB + st * 8, ph);
            issue(st, kb + 3);
        }
        st++;
        if (st == 3) { st = 0; ph ^= 1; }
    }

    #pragma unroll
    for (int rb = 0; rb < 2; rb++) {
        lsum[rb][0] += __shfl_xor_sync(0xffffffffu, lsum[rb][0], 1);
        lsum[rb][0] += __shfl_xor_sync(0xffffffffu, lsum[rb][0], 2);
        lsum[rb][1] += __shfl_xor_sync(0xffffffffu, lsum[rb][1], 1);
        lsum[rb][1] += __shfl_xor_sync(0xffffffffu, lsum[rb][1], 2);
    }

    float* xch = (float*)sma;
    __syncthreads();
    if (wk == 1) {
        float* dst = xch + (wq * 32 + lane) * 68;
        #pragma unroll
        for (int rb = 0; rb < 2; rb++)
            #pragma unroll
            for (int j = 0; j < 8; j++) {
                dst[rb * 32 + j * 4 + 0] = oa[rb][j][0];
                dst[rb * 32 + j * 4 + 1] = oa[rb][j][1];
                dst[rb * 32 + j * 4 + 2] = oa[rb][j][2];
                dst[rb * 32 + j * 4 + 3] = oa[rb][j][3];
            }
        dst[64] = lsum[0][0]; dst[65] = lsum[0][1];
        dst[66] = lsum[1][0]; dst[67] = lsum[1][1];
    }
    __syncthreads();
    if (wk == 1) return;

    {
        const float* src = xch + (wq * 32 + lane) * 68;
        #pragma unroll
        for (int rb = 0; rb < 2; rb++)
            #pragma unroll
            for (int j = 0; j < 8; j++) {
                oa[rb][j][0] += src[rb * 32 + j * 4 + 0];
                oa[rb][j][1] += src[rb * 32 + j * 4 + 1];
                oa[rb][j][2] += src[rb * 32 + j * 4 + 2];
                oa[rb][j][3] += src[rb * 32 + j * 4 + 3];
            }
        lsum[0][0] += src[64]; lsum[0][1] += src[65];
        lsum[1][0] += src[66]; lsum[1][1] += src[67];
    }

    #pragma unroll
    for (int rb = 0; rb < 2; rb++) {
        const float inv0 = 1.0f / lsum[rb][0], inv1 = 1.0f / lsum[rb][1];
        const int t0 = qb * 128 + wq * 32 + rb * 16 + (lane >> 2);
        const int t1 = t0 + 8;
        const uint32_t pan = (uint32_t)((b * 16 + qb) * 16 + h);
        const int r0 = t0 & 127, r1 = t1 & 127;
        #pragma unroll
        for (int j = 0; j < 8; j++) {
            const int cp = j * 4 + (lane & 3);
            g_ah[panel_u32(pan, r0, cp)] = pack_h2(oa[rb][j][0] * inv0, oa[rb][j][1] * inv0);
            g_ah[panel_u32(pan, r1, cp)] = pack_h2(oa[rb][j][2] * inv1, oa[rb][j][3] * inv1);
        }
    }
}

// ================= launch =================
extern "C" void kernel_launch(void* const* d_in, const int* in_sizes, int n_in,
                              void* d_out, int out_size) {
    const float* x    = (const float*)d_in[0];
    const float* qkvo = (const float*)d_in[1];
    const float* qw   = (const float*)d_in[2];
    const float* kw   = (const float*)d_in[3];
    float* out = (float*)d_out;

    void *p_xhi, *p_xlo, *p_wh, *p_ah;
    cudaGetSymbolAddress(&p_xhi, g_xhi); cudaGetSymbolAddress(&p_xlo, g_xlo);
    cudaGetSymbolAddress(&p_wh, g_wh);
    cudaGetSymbolAddress(&p_ah, g_ah);

    const int GEMM1_SMEM = 4 * 49152 + 128;
    const int GEMM2_SMEM = 4 * 32768 + 128;
    const int ATTN_SMEM  = 114688 + 128;
    cudaFuncSetAttribute((const void*)gemm_f16x2<true, true>,   cudaFuncAttributeMaxDynamicSharedMemorySize, GEMM1_SMEM);
    cudaFuncSetAttribute((const void*)gemm_f16x2<false, false>, cudaFuncAttributeMaxDynamicSharedMemorySize, GEMM2_SMEM);
    cudaFuncSetAttribute((const void*)attn_mma, cudaFuncAttributeMaxDynamicSharedMemorySize, ATTN_SMEM);

    // 0) fused prep: x hi/lo panels + weight panels + RoPE table (917504 threads)
    prep_all<<<3584, 256>>>(x, qkvo, nullptr);

    // 1) persistent QKV projection + fused RMSNorm/RoPE -> Q/K/V fp16 panels
    gemm_f16x2<true, true><<<148, 512, GEMM1_SMEM>>>(
        (const uint32_t*)p_xhi, (const uint32_t*)p_xlo,
        (const uint32_t*)p_wh, nullptr, QKVN, qw, kw, 12, 384);

    // 2) tensor-core causal flash attention -> g_ah panels
    attn_mma<<<dim3(SEQ / 128, NH, BATCH), 256, ATTN_SMEM>>>();

    // 3) persistent O projection (A single plane; weight panels start at nt=12)
    gemm_f16x2<false, false><<<148, 512, GEMM2_SMEM>>>(
        (const uint32_t*)p_ah, nullptr,
        (const uint32_t*)p_wh + (size_t)12 * 16 * 4096, out, DM, nullptr, nullptr, 8, 256);
}

// round 17
// speedup vs baseline: 1.2970x; 1.0251x over previous
#include <cuda_runtime.h>
#include <cuda_fp16.h>
#include <math.h>
#include <stdint.h>

#define BATCH 2
#define SEQ   2048
#define DM    1024
#define NH    16
#define NKV   4
#define DK    64
#define QKVN  1536
#define ROWS  (BATCH*SEQ)
#define GROUPS (NH/NKV)
#define GK    1024

// ---------------- scratch: pre-swizzled 16KB panels (128 rows x 64 fp16 cols) ----------------
__device__ __align__(128) uint32_t g_xhi[ROWS * GK / 2],  g_xlo[ROWS * GK / 2];
__device__ __align__(128) uint32_t g_wh [2560 * GK / 2];
__device__ __align__(128) uint32_t g_ah [ROWS * DM / 2];
__device__ __align__(128) uint32_t g_qh [BATCH * NH  * SEQ * DK / 2];
__device__ __align__(128) uint32_t g_kh [BATCH * NKV * SEQ * DK / 2];
__device__ __align__(128) uint32_t g_vh [BATCH * NKV * SEQ * DK / 2];
__device__ __align__(16)  float2   g_rope[SEQ * 32];

// ================= helpers =================
__device__ __forceinline__ uint32_t smem_to_u32(const void* p) {
    uint32_t a;
    asm("{ .reg .u64 t; cvta.to.shared.u64 t, %1; cvt.u32.u64 %0, t; }" : "=r"(a) : "l"(p));
    return a;
}
__device__ __forceinline__ float ex2(float x) {
    float r; asm("ex2.approx.f32 %0, %1;" : "=f"(r) : "f"(x)); return r;
}
__device__ __forceinline__ uint32_t pack_h2(float lo, float hi) {
    uint32_t r;
    asm("cvt.rn.f16x2.f32 %0, %1, %2;" : "=r"(r) : "f"(hi), "f"(lo));
    return r;
}
__device__ __forceinline__ void splitH2(float2 v, uint32_t& hi, uint32_t& lo) {
    __half h0 = __float2half_rn(v.x);
    __half h1 = __float2half_rn(v.y);
    float r0 = v.x - __half2float(h0);
    float r1 = v.y - __half2float(h1);
    hi = (uint32_t)__half_as_ushort(h0) | ((uint32_t)__half_as_ushort(h1) << 16);
    lo = pack_h2(r0, r1);
}
__device__ __forceinline__ uint32_t panel_u32(uint32_t panel, int r, int cp) {
    int cl = cp >> 2;
    return panel * 4096u + (uint32_t)(r * 32 + ((cl ^ (r & 7)) << 2) + (cp & 3));
}

__device__ __forceinline__ void bulk_cp(uint32_t dst, const void* src, uint32_t bytes, uint32_t mbar) {
    asm volatile("cp.async.bulk.shared::cta.global.mbarrier::complete_tx::bytes [%0], [%1], %2, [%3];"
        :: "r"(dst), "l"(src), "r"(bytes), "r"(mbar) : "memory");
}
#define MBARRIER_INIT(mbar, count) \
    asm volatile("mbarrier.init.shared.b64 [%0], %1;" \
        :: "r"((uint32_t)(mbar)), "r"((uint32_t)(count)) : "memory")
#define MBARRIER_EXPECT_TX(mbar, bytes) \
    asm volatile("mbarrier.arrive.expect_tx.shared.b64 _, [%0], %1;" \
        :: "r"((uint32_t)(mbar)), "r"((uint32_t)(bytes)) : "memory")
#define MBARRIER_ARRIVE(mbar) \
    asm volatile("mbarrier.arrive.shared.b64 _, [%0];" \
        :: "r"((uint32_t)(mbar)) : "memory")
#define MBARRIER_WAIT(mbar_addr, parity) do { \
    uint32_t _mbar = (uint32_t)(mbar_addr); \
    uint32_t _par = (uint32_t)(parity); \
    uint32_t _done; \
    asm volatile("{\n\t.reg .pred p;\n\t" \
        "mbarrier.try_wait.parity.acquire.cta.shared::cta.b64 p, [%1], %2;\n\t" \
        "selp.b32 %0, 1, 0, p;\n\t}" : "=r"(_done) : "r"(_mbar), "r"(_par) : "memory"); \
    if (!_done) { \
        asm volatile("{\n\t.reg .pred P1;\n\t" \
            "WAIT_LOOP_%=:\n\t" \
            "mbarrier.try_wait.parity.acquire.cta.shared::cta.b64 P1, [%0], %1, 0x989680;\n\t" \
            "@P1 bra.uni WAIT_DONE_%=;\n\t" \
            "bra.uni WAIT_LOOP_%=;\n\t" \
            "WAIT_DONE_%=:\n\t}" :: "r"(_mbar), "r"(_par) : "memory"); \
    } \
} while(0)

__device__ __forceinline__ void ldsm4(uint32_t* r, uint32_t addr) {
    asm volatile("ldmatrix.sync.aligned.m8n8.x4.shared.b16 {%0,%1,%2,%3}, [%4];"
        : "=r"(r[0]), "=r"(r[1]), "=r"(r[2]), "=r"(r[3]) : "r"(addr));
}
__device__ __forceinline__ void ldsm4t(uint32_t* r, uint32_t addr) {
    asm volatile("ldmatrix.sync.aligned.m8n8.x4.trans.shared.b16 {%0,%1,%2,%3}, [%4];"
        : "=r"(r[0]), "=r"(r[1]), "=r"(r[2]), "=r"(r[3]) : "r"(addr));
}
__device__ __forceinline__ void mma16816h(float* c, const uint32_t* a, uint32_t b0, uint32_t b1) {
    asm volatile("mma.sync.aligned.m16n8k16.row.col.f32.f16.f16.f32 "
        "{%0,%1,%2,%3}, {%4,%5,%6,%7}, {%8,%9}, {%0,%1,%2,%3};"
        : "+f"(c[0]), "+f"(c[1]), "+f"(c[2]), "+f"(c[3])
        : "r"(a[0]), "r"(a[1]), "r"(a[2]), "r"(a[3]), "r"(b0), "r"(b1));
}

// ================= fused prep: x split + w pack + RoPE table =================
#define XG 524288
#define WG 327680
__global__ void prep_all(const float* __restrict__ x, const float* __restrict__ wsrc) {
    int i = blockIdx.x * blockDim.x + threadIdx.x;
    if (i < XG) {
        int row = i >> 7, cp0 = (i & 127) * 4;
        const float4* s = (const float4*)(x + (size_t)row * 1024 + cp0 * 2);
        float4 a = s[0], b = s[1];
        uint32_t h0, h1, h2, h3, l0, l1, l2, l3;
        splitH2(make_float2(a.x, a.y), h0, l0);
        splitH2(make_float2(a.z, a.w), h1, l1);
        splitH2(make_float2(b.x, b.y), h2, l2);
        splitH2(make_float2(b.z, b.w), h3, l3);
        uint32_t idx = panel_u32((uint32_t)((row >> 7) * 16 + (cp0 >> 5)), row & 127, cp0 & 31);
        *(uint4*)&g_xhi[idx] = make_uint4(h0, h1, h2, h3);
        *(uint4*)&g_xlo[idx] = make_uint4(l0, l1, l2, l3);
    } else if (i < XG + WG) {
        int g = i - XG;
        int row = g >> 7, cp0 = (g & 127) * 4;
        const float4* s = (const float4*)(wsrc + (size_t)row * 1024 + cp0 * 2);
        float4 a = s[0], b = s[1];
        uint32_t idx = panel_u32((uint32_t)((row >> 7) * 16 + (cp0 >> 5)), row & 127, cp0 & 31);
        *(uint4*)&g_wh[idx] = make_uint4(pack_h2(a.x, a.y), pack_h2(a.z, a.w),
                                         pack_h2(b.x, b.y), pack_h2(b.z, b.w));
    } else {
        int e = i - XG - WG;
        int t = e >> 5, li = e & 31;
        float invf = __powf(10000.0f, -(float)(2 * li) / (float)DK);
        float sv, cv;
        sincosf((float)t * invf, &sv, &cv);
        g_rope[t * 32 + li] = make_float2(cv, sv);
    }
}

// ================= persistent fp16 GEMM, 128x128 tiles, 256 threads, NS-stage bulk =================
// warp grid 4m x 2n; warp tile 32m x 64n. 2 CTAs/SM (smem <= 96.2KB, regs <= 128).
template<bool FUSE_QKV, bool ALO, int NS>
__global__ __launch_bounds__(256, 2) void gemm_f16x2(
        const uint32_t* __restrict__ Ahi, const uint32_t* __restrict__ Alo,
        const uint32_t* __restrict__ Bh, float* __restrict__ C, int N,
        const float* __restrict__ qw, const float* __restrict__ kw,
        int NT, int NTILES) {
    extern __shared__ char smc[];
    const uint32_t sb = smem_to_u32(smc);
    constexpr uint32_t STAGE = ALO ? 49152u : 32768u;
    const uint32_t FB = sb + NS * STAGE;
    const uint32_t EB = FB + NS * 8;
    const int tid = threadIdx.x;
    const int wid = tid >> 5, lane = tid & 31;
    const int wm = wid & 3, wn = wid >> 2;

    if (tid == 0) {
        #pragma unroll
        for (int s = 0; s < NS; s++) { MBARRIER_INIT(FB + s * 8, 1); MBARRIER_INIT(EB + s * 8, 256); }
    }
    __syncthreads();

    auto issue_kg = [&](int kg) {
        int tile = blockIdx.x + (kg >> 4) * gridDim.x;
        if (tile >= NTILES) return;
        int kt = kg & 15;
        int mt = tile / NT, nt = tile % NT;
        int s = kg % NS;
        MBARRIER_EXPECT_TX(FB + s * 8, STAGE);
        bulk_cp(sb + s * STAGE, Ahi + (size_t)(mt * 16 + kt) * 4096, 16384, FB + s * 8);
        if (ALO)
            bulk_cp(sb + s * STAGE + 16384u, Alo + (size_t)(mt * 16 + kt) * 4096, 16384, FB + s * 8);
        bulk_cp(sb + s * STAGE + (ALO ? 32768u : 16384u),
                Bh + (size_t)(nt * 16 + kt) * 4096, 16384, FB + s * 8);
    };
    if (tid == 0) {
        #pragma unroll
        for (int i = 0; i < NS; i++) issue_kg(i);
    }

    const int lrow = lane & 15, khalf = lane >> 4;
    const int crow = lane >> 2, ccl = lane & 3;

    int tl = 0;
    for (int tile = blockIdx.x; tile < NTILES; tile += gridDim.x, tl++) {
        const int mt = tile / NT, nt = tile % NT;

        float acc[2][8][4];
        #pragma unroll
        for (int i = 0; i < 2; i++)
            #pragma unroll
            for (int j = 0; j < 8; j++)
                #pragma unroll
                for (int e = 0; e < 4; e++) acc[i][j][e] = 0.0f;

        for (int kt = 0; kt < 16; kt++) {
            const int kg = tl * 16 + kt;
            const int s = kg % NS, ph = (kg / NS) & 1;
            MBARRIER_WAIT(FB + s * 8, ph);
            const uint32_t base = sb + (uint32_t)s * STAGE;
            const uint32_t aHi = base;
            const uint32_t aLo = base + 16384u;
            const uint32_t bH  = base + (ALO ? 32768u : 16384u);

            #pragma unroll
            for (int ks = 0; ks < 4; ks++) {
                const int c = ks * 2 + khalf;
                uint32_t ah[2][4], al[2][4];
                #pragma unroll
                for (int ma = 0; ma < 2; ma++) {
                    int r = wm * 32 + ma * 16 + lrow;
                    uint32_t off = (uint32_t)(r * 128 + ((c ^ (r & 7)) << 4));
                    ldsm4(ah[ma], aHi + off);
                    if (ALO) ldsm4(al[ma], aLo + off);
                }
                #pragma unroll
                for (int nb = 0; nb < 4; nb++) {
                    int r = wn * 64 + nb * 16 + lrow;
                    uint32_t off = (uint32_t)(r * 128 + ((c ^ (r & 7)) << 4));
                    uint32_t bh[4];
                    ldsm4(bh, bH + off);
                    #pragma unroll
                    for (int ma = 0; ma < 2; ma++) {
                        mma16816h(acc[ma][nb * 2],     ah[ma], bh[0], bh[2]);
                        if (ALO) mma16816h(acc[ma][nb * 2], al[ma], bh[0], bh[2]);
                        mma16816h(acc[ma][nb * 2 + 1], ah[ma], bh[1], bh[3]);
                        if (ALO) mma16816h(acc[ma][nb * 2 + 1], al[ma], bh[1], bh[3]);
                    }
                }
            }
            MBARRIER_ARRIVE(EB + s * 8);
            if (tid == 0) {
                MBARRIER_WAIT(EB + s * 8, ph);
                issue_kg(kg + NS);
            }
        }

        if (!FUSE_QKV) {
            const int ccol = ccl * 2;
            #pragma unroll
            for (int ma = 0; ma < 2; ma++) {
                #pragma unroll
                for (int na = 0; na < 8; na++) {
                    int r = mt * 128 + wm * 32 + ma * 16 + crow;
                    int cc = nt * 128 + wn * 64 + na * 8 + ccol;
                    *(float2*)&C[(size_t)r * N + cc]       = make_float2(acc[ma][na][0], acc[ma][na][1]);
                    *(float2*)&C[(size_t)(r + 8) * N + cc] = make_float2(acc[ma][na][2], acc[ma][na][3]);
                }
            }
            continue;
        }

        // ---------- fused RMSNorm + RoPE(table) + fp16 panel epilogue ----------
        const int slot = nt * 2 + wn;

        if (slot >= NH + NKV) {            // V panels
            const int hv = slot - NH - NKV;
            #pragma unroll
            for (int ma = 0; ma < 2; ma++)
                #pragma unroll
                for (int rr = 0; rr < 2; rr++) {
                    const int row = mt * 128 + wm * 32 + ma * 16 + rr * 8 + crow;
                    const int b = row >> 11, t = row & (SEQ - 1);
                    const uint32_t pan = (uint32_t)((b * NKV + hv) * 16 + (t >> 7));
                    const int r = t & 127;
                    #pragma unroll
                    for (int na = 0; na < 8; na++)
                        g_vh[panel_u32(pan, r, na * 4 + ccl)] =
                            pack_h2(acc[ma][na][rr * 2], acc[ma][na][rr * 2 + 1]);
                }
            continue;
        }

        const bool isQ = (slot < NH);
        const float* w = isQ ? qw : kw;
        float w0[8], w1[8];
        #pragma unroll
        for (int na = 0; na < 8; na++) {
            const int i2 = na * 4 + ccl;
            w0[na] = w[2 * i2];
            w1[na] = w[2 * i2 + 1];
        }
        const float qs = 0.125f * 1.4426950408889634f;

        #pragma unroll
        for (int ma = 0; ma < 2; ma++)
            #pragma unroll
            for (int rr = 0; rr < 2; rr++) {
                const int row = mt * 128 + wm * 32 + ma * 16 + rr * 8 + crow;
                const int b = row >> 11, t = row & (SEQ - 1);

                float ss = 0.0f;
                #pragma unroll
                for (int na = 0; na < 8; na++) {
                    float v0 = acc[ma][na][rr * 2], v1 = acc[ma][na][rr * 2 + 1];
                    ss += v0 * v0 + v1 * v1;
                }
                ss += __shfl_xor_sync(0xffffffffu, ss, 1);
                ss += __shfl_xor_sync(0xffffffffu, ss, 2);
                const float rnorm = rsqrtf(ss * (1.0f / DK) + 1.1920929e-07f);

                const uint32_t pan = isQ
                    ? (uint32_t)((b * NH + slot) * 16 + (t >> 7))
                    : (uint32_t)((b * NKV + (slot - NH)) * 16 + (t >> 7));
                const int r = t & 127;

                #pragma unroll
                for (int na = 0; na < 8; na++) {
                    float y0 = acc[ma][na][rr * 2]     * rnorm * w0[na];
                    float y1 = acc[ma][na][rr * 2 + 1] * rnorm * w1[na];
                    float2 cs = g_rope[t * 32 + na * 4 + ccl];
                    float o0 = y0 * cs.x - y1 * cs.y;
                    float o1 = y0 * cs.y + y1 * cs.x;
                    if (isQ) g_qh[panel_u32(pan, r, na * 4 + ccl)] = pack_h2(o0 * qs, o1 * qs);
                    else     g_kh[panel_u32(pan, r, na * 4 + ccl)] = pack_h2(o0, o1);
                }
            }
    }
}

// ================= tensor-core causal flash attention (unchanged from R16) =================
__global__ __launch_bounds__(256, 1) void attn_mma() {
    extern __shared__ char sma[];
    const uint32_t sb = smem_to_u32(sma);
    const uint32_t FB = sb + 114688u;
    const uint32_t EB = FB + 32u;
    const int tid = threadIdx.x;
    const int wid = tid >> 5, lane = tid & 31;
    const int wq = wid >> 1, wk = wid & 1;
    const int qb = (int)gridDim.x - 1 - (int)blockIdx.x;
    const int h  = blockIdx.y, b = blockIdx.z;
    const int kvh = h / GROUPS;
    const int nkb = qb + 1;

    if (tid == 0) {
        #pragma unroll
        for (int s = 0; s < 3; s++) { MBARRIER_INIT(FB + s * 8, 1); MBARRIER_INIT(EB + s * 8, 256); }
        MBARRIER_INIT(FB + 24, 1);
    }
    __syncthreads();

    const uint32_t qpan  = (uint32_t)((b * NH + h) * 16 + qb);
    const uint32_t kvpan = (uint32_t)((b * NKV + kvh) * 16);

    auto issue = [&](int s, int kb) {
        MBARRIER_EXPECT_TX(FB + s * 8, 32768);
        bulk_cp(sb + s * 32768u,          g_kh + (size_t)(kvpan + kb) * 4096, 16384, FB + s * 8);
        bulk_cp(sb + s * 32768u + 16384u, g_vh + (size_t)(kvpan + kb) * 4096, 16384, FB + s * 8);
    };
    if (tid == 0) {
        MBARRIER_EXPECT_TX(FB + 24, 16384);
        bulk_cp(sb + 98304u, g_qh + (size_t)qpan * 4096, 16384, FB + 24);
        issue(0, 0);
        if (nkb > 1) issue(1, 1);
        if (nkb > 2) issue(2, 2);
    }

    MBARRIER_WAIT(FB + 24, 0);
    const int lrow = lane & 15, khalf = lane >> 4;
    uint32_t qh[2][4][4];
    #pragma unroll
    for (int rb = 0; rb < 2; rb++) {
        const int r = wq * 32 + rb * 16 + lrow;
        #pragma unroll
        for (int ks = 0; ks < 4; ks++) {
            const int c = ks * 2 + khalf;
            uint32_t off = (uint32_t)(r * 128 + ((c ^ (r & 7)) << 4));
            ldsm4(qh[rb][ks], sb + 98304u + off);
        }
    }

    float oa[2][8][4];
    #pragma unroll
    for (int rb = 0; rb < 2; rb++)
        #pragma unroll
        for (int j = 0; j < 8; j++)
            #pragma unroll
            for (int e = 0; e < 4; e++) oa[rb][j][e] = 0.0f;
    float lsum[2][2] = {{0.0f, 0.0f}, {0.0f, 0.0f}};

    const int vrow_base = ((lane >> 3) & 1) * 8 + (lane & 7);
    const int vkh = lane >> 4;

    int st = 0, ph = 0;
    for (int kb = 0; kb < nkb; kb++) {
        MBARRIER_WAIT(FB + st * 8, ph);
        const uint32_t kH = sb + (uint32_t)st * 32768u;
        const uint32_t vH = kH + 16384u;

        float sc[2][8][4];
        #pragma unroll
        for (int rb = 0; rb < 2; rb++)
            #pragma unroll
            for (int j = 0; j < 8; j++)
                #pragma unroll
                for (int e = 0; e < 4; e++) sc[rb][j][e] = 0.0f;

        #pragma unroll
        for (int ks = 0; ks < 4; ks++) {
            const int c = ks * 2 + khalf;
            #pragma unroll
            for (int nb = 0; nb < 4; nb++) {
                int r = wk * 64 + nb * 16 + lrow;
                uint32_t off = (uint32_t)(r * 128 + ((c ^ (r & 7)) << 4));
                uint32_t kh[4];
                ldsm4(kh, kH + off);
                #pragma unroll
                for (int rb = 0; rb < 2; rb++) {
                    mma16816h(sc[rb][2 * nb],     qh[rb][ks], kh[0], kh[2]);
                    mma16816h(sc[rb][2 * nb + 1], qh[rb][ks], kh[1], kh[3]);
                }
            }
        }

        if (kb == qb) {
            #pragma unroll
            for (int rb = 0; rb < 2; rb++) {
                const int g0 = qb * 128 + wq * 32 + rb * 16 + (lane >> 2);
                const int g1 = g0 + 8;
                #pragma unroll
                for (int j = 0; j < 8; j++) {
                    const int c0 = kb * 128 + wk * 64 + 8 * j + (lane & 3) * 2;
                    const int c1 = c0 + 1;
                    if (c0 > g0) sc[rb][j][0] = -INFINITY;
                    if (c1 > g0) sc[rb][j][1] = -INFINITY;
                    if (c0 > g1) sc[rb][j][2] = -INFINITY;
                    if (c1 > g1) sc[rb][j][3] = -INFINITY;
                }
            }
        }

        #pragma unroll
        for (int rb = 0; rb < 2; rb++) {
            #pragma unroll
            for (int j = 0; j < 8; j++) {
                sc[rb][j][0] = ex2(sc[rb][j][0]);
                sc[rb][j][1] = ex2(sc[rb][j][1]);
                sc[rb][j][2] = ex2(sc[rb][j][2]);
                sc[rb][j][3] = ex2(sc[rb][j][3]);
                lsum[rb][0] += sc[rb][j][0] + sc[rb][j][1];
                lsum[rb][1] += sc[rb][j][2] + sc[rb][j][3];
            }
        }

        uint32_t pa[2][4][4];
        #pragma unroll
        for (int rb = 0; rb < 2; rb++)
            #pragma unroll
            for (int kk = 0; kk < 4; kk++) {
                pa[rb][kk][0] = pack_h2(sc[rb][2 * kk][0],     sc[rb][2 * kk][1]);
                pa[rb][kk][1] = pack_h2(sc[rb][2 * kk][2],     sc[rb][2 * kk][3]);
                pa[rb][kk][2] = pack_h2(sc[rb][2 * kk + 1][0], sc[rb][2 * kk + 1][1]);
                pa[rb][kk][3] = pack_h2(sc[rb][2 * kk + 1][2], sc[rb][2 * kk + 1][3]);
            }

        #pragma unroll
        for (int kk = 0; kk < 4; kk++) {
            const int vr = wk * 64 + kk * 16 + vrow_base;
            #pragma unroll
            for (int ng = 0; ng < 4; ng++) {
                const int vc = ng * 2 + vkh;
                uint32_t off = (uint32_t)(vr * 128 + ((vc ^ (vr & 7)) << 4));
                uint32_t vh[4];
                ldsm4t(vh, vH + off);
                #pragma unroll
                for (int rb = 0; rb < 2; rb++) {
                    mma16816h(oa[rb][2 * ng],     pa[rb][kk], vh[0], vh[1]);
                    mma16816h(oa[rb][2 * ng + 1], pa[rb][kk], vh[2], vh[3]);
                }
            }
        }

        MBARRIER_ARRIVE(EB + st * 8);
        if (tid == 0 && kb + 3 < nkb) {
            MBARRIER_WAIT(EB + st * 8, ph);
            issue(st, kb + 3);
        }
        st++;
        if (st == 3) { st = 0; ph ^= 1; }
    }

    #pragma unroll
    for (int rb = 0; rb < 2; rb++) {
        lsum[rb][0] += __shfl_xor_sync(0xffffffffu, lsum[rb][0], 1);
        lsum[rb][0] += __shfl_xor_sync(0xffffffffu, lsum[rb][0], 2);
        lsum[rb][1] += __shfl_xor_sync(0xffffffffu, lsum[rb][1], 1);
        lsum[rb][1] += __shfl_xor_sync(0xffffffffu, lsum[rb][1], 2);
    }

    float* xch = (float*)sma;
    __syncthreads();
    if (wk == 1) {
        float* dst = xch + (wq * 32 + lane) * 68;
        #pragma unroll
        for (int rb = 0; rb < 2; rb++)
            #pragma unroll
            for (int j = 0; j < 8; j++) {
                dst[rb * 32 + j * 4 + 0] = oa[rb][j][0];
                dst[rb * 32 + j * 4 + 1] = oa[rb][j][1];
                dst[rb * 32 + j * 4 + 2] = oa[rb][j][2];
                dst[rb * 32 + j * 4 + 3] = oa[rb][j][3];
            }
        dst[64] = lsum[0][0]; dst[65] = lsum[0][1];
        dst[66] = lsum[1][0]; dst[67] = lsum[1][1];
    }
    __syncthreads();
    if (wk == 1) return;

    {
        const float* src = xch + (wq * 32 + lane) * 68;
        #pragma unroll
        for (int rb = 0; rb < 2; rb++)
            #pragma unroll
            for (int j = 0; j < 8; j++) {
                oa[rb][j][0] += src[rb * 32 + j * 4 + 0];
                oa[rb][j][1] += src[rb * 32 + j * 4 + 1];
                oa[rb][j][2] += src[rb * 32 + j * 4 + 2];
                oa[rb][j][3] += src[rb * 32 + j * 4 + 3];
            }
        lsum[0][0] += src[64]; lsum[0][1] += src[65];
        lsum[1][0] += src[66]; lsum[1][1] += src[67];
    }

    #pragma unroll
    for (int rb = 0; rb < 2; rb++) {
        const float inv0 = 1.0f / lsum[rb][0], inv1 = 1.0f / lsum[rb][1];
        const int t0 = qb * 128 + wq * 32 + rb * 16 + (lane >> 2);
        const int t1 = t0 + 8;
        const uint32_t pan = (uint32_t)((b * 16 + qb) * 16 + h);
        const int r0 = t0 & 127, r1 = t1 & 127;
        #pragma unroll
        for (int j = 0; j < 8; j++) {
            const int cp = j * 4 + (lane & 3);
            g_ah[panel_u32(pan, r0, cp)] = pack_h2(oa[rb][j][0] * inv0, oa[rb][j][1] * inv0);
            g_ah[panel_u32(pan, r1, cp)] = pack_h2(oa[rb][j][2] * inv1, oa[rb][j][3] * inv1);
        }
    }
}

// ================= launch =================
extern "C" void kernel_launch(void* const* d_in, const int* in_sizes, int n_in,
                              void* d_out, int out_size) {
    const float* x    = (const float*)d_in[0];
    const float* qkvo = (const float*)d_in[1];
    const float* qw   = (const float*)d_in[2];
    const float* kw   = (const float*)d_in[3];
    float* out = (float*)d_out;

    void *p_xhi, *p_xlo, *p_wh, *p_ah;
    cudaGetSymbolAddress(&p_xhi, g_xhi); cudaGetSymbolAddress(&p_xlo, g_xlo);
    cudaGetSymbolAddress(&p_wh, g_wh);
    cudaGetSymbolAddress(&p_ah, g_ah);

    const int GEMM1_SMEM = 2 * 49152 + 128;   // 2-stage ALO: 98432 -> 2 CTAs/SM
    const int GEMM2_SMEM = 3 * 32768 + 128;   // 3-stage:     98432 -> 2 CTAs/SM
    const int ATTN_SMEM  = 114688 + 128;
    cudaFuncSetAttribute((const void*)gemm_f16x2<true, true, 2>,   cudaFuncAttributeMaxDynamicSharedMemorySize, GEMM1_SMEM);
    cudaFuncSetAttribute((const void*)gemm_f16x2<false, false, 3>, cudaFuncAttributeMaxDynamicSharedMemorySize, GEMM2_SMEM);
    cudaFuncSetAttribute((const void*)attn_mma, cudaFuncAttributeMaxDynamicSharedMemorySize, ATTN_SMEM);

    // 0) fused prep: x hi/lo panels + weight panels + RoPE table
    prep_all<<<3584, 256>>>(x, qkvo);

    // 1) persistent QKV projection + fused RMSNorm/RoPE -> Q/K/V fp16 panels (2 CTAs/SM)
    gemm_f16x2<true, true, 2><<<296, 256, GEMM1_SMEM>>>(
        (const uint32_t*)p_xhi, (const uint32_t*)p_xlo,
        (const uint32_t*)p_wh, nullptr, QKVN, qw, kw, 12, 384);

    // 2) tensor-core causal flash attention -> g_ah panels
    attn_mma<<<dim3(SEQ / 128, NH, BATCH), 256, ATTN_SMEM>>>();

    // 3) O projection (A single plane; weight panels start at nt=12), 2 CTAs/SM
    gemm_f16x2<false, false, 3><<<256, 256, GEMM2_SMEM>>>(
        (const uint32_t*)p_ah, nullptr,
        (const uint32_t*)p_wh + (size_t)12 * 16 * 4096, out, DM, nullptr, nullptr, 8, 256);
}